// round 13
// baseline (speedup 1.0000x reference)
#include <cuda_runtime.h>
#include <cuda_fp16.h>
#include <cstdint>

#define BB 64
#define CC 64
#define TT 2048
#define HH 128
#define GG 512   // 4H
#define H2 256   // 2H

// Scratch (device globals — no runtime allocation allowed)
__device__ __half g_z2[2][8][TT][GG][8];    // 256 MiB z, chain-interleaved [dir][bg][t][g][n]
__device__ __half g_y[BB][TT][H2];          // 64 MiB [h_fwd | h_bwd]
__device__ float  g_scores[BB][TT];         // attention logits
__device__ __align__(16) __half g_Wa_h[H2 * H2];    // Wa fp16, row-major [g][k]
__device__ __align__(16) __half g_W1h[1024 * CC];   // [Wih_f; Wih_b] fp16 row-major
__device__ float  g_b1[1024];               // bih+bhh per dir, concatenated

// ---------------- helpers ----------------
__device__ __forceinline__ float fast_ex2(float x) {
    float y; asm("ex2.approx.f32 %0, %1;" : "=f"(y) : "f"(x)); return y;
}
#define LOG2E 1.4426950408889634f
__device__ __forceinline__ float ftanh(float x) {     // MUFU.TANH f32
    float y; asm("tanh.approx.f32 %0, %1;" : "=f"(y) : "f"(x)); return y;
}
__device__ __forceinline__ __half2 u2h(unsigned u) {
    return *reinterpret_cast<__half2*>(&u);
}
__device__ __forceinline__ uint32_t h2u(__half2 h) {
    return *reinterpret_cast<uint32_t*>(&h);
}
__device__ __forceinline__ __half2 h2tanh_(__half2 x) {  // MUFU.TANH f16x2
    uint32_t xi = h2u(x), yi;
    asm("tanh.approx.f16x2 %0, %1;" : "=r"(yi) : "r"(xi));
    return u2h(yi);
}

// m16n8k16 row.col f16 -> f32 (K1/K3)
__device__ __forceinline__ void mma16816(float* d, const uint32_t* a,
                                         uint32_t b0, uint32_t b1, const float* c) {
    asm volatile(
        "mma.sync.aligned.m16n8k16.row.col.f32.f16.f16.f32 "
        "{%0,%1,%2,%3}, {%4,%5,%6,%7}, {%8,%9}, {%10,%11,%12,%13};"
        : "=f"(d[0]), "=f"(d[1]), "=f"(d[2]), "=f"(d[3])
        : "r"(a[0]), "r"(a[1]), "r"(a[2]), "r"(a[3]),
          "r"(b0), "r"(b1),
          "f"(c[0]), "f"(c[1]), "f"(c[2]), "f"(c[3]));
}

// m16n8k16 row.col f16 -> f16 (K2: short accumulator chains, D=C in-place)
__device__ __forceinline__ void mma16816h(uint32_t* d, const uint32_t* a,
                                          uint32_t b0, uint32_t b1) {
    asm volatile(
        "mma.sync.aligned.m16n8k16.row.col.f16.f16.f16.f16 "
        "{%0,%1}, {%2,%3,%4,%5}, {%6,%7}, {%0,%1};"
        : "+r"(d[0]), "+r"(d[1])
        : "r"(a[0]), "r"(a[1]), "r"(a[2]), "r"(a[3]),
          "r"(b0), "r"(b1));
}

// ---------------- prep: Wa + W1 + biases in one kernel ----------------
__global__ void __launch_bounds__(256) p_prep(
    const float* __restrict__ Wa,
    const float* __restrict__ Wf, const float* __restrict__ Wb,
    const float* __restrict__ bif, const float* __restrict__ bhf,
    const float* __restrict__ bib, const float* __restrict__ bhb)
{
    int i = blockIdx.x * 256 + threadIdx.x;           // 0..65535
    g_Wa_h[i] = __float2half(__ldg(Wa + i));
    g_W1h[i]  = __float2half(i < 32768 ? __ldg(Wf + i) : __ldg(Wb + i - 32768));
    if (i < 512)       g_b1[i] = __ldg(bif + i) + __ldg(bhf + i);
    else if (i < 1024) g_b1[i] = __ldg(bib + i - 512) + __ldg(bhb + i - 512);
}

// ---------------- K1: z = x_tile @ W1^T + bias via mma.sync ----------------
#define K1_WS   0
#define K1_XS   147456
#define K1_BS   164352
#define K1_TOT  168448

__global__ void __launch_bounds__(256) k1_mma(const float* __restrict__ x)
{
    extern __shared__ __align__(16) char smem[];
    const int tid = threadIdx.x;
    const int t0 = blockIdx.x * 128;
    const int b  = blockIdx.y;

    {
        const uint4* src = reinterpret_cast<const uint4*>(g_W1h);
        #pragma unroll
        for (int i = 0; i < 32; i++) {
            int idx = i * 256 + tid;
            int r = idx >> 3, c = idx & 7;
            *reinterpret_cast<uint4*>(smem + K1_WS + r * 144 + c * 16) = __ldg(src + idx);
        }
    }
    #pragma unroll
    for (int i = 0; i < 32; i++) {
        int idx = i * 256 + tid;
        int c = idx >> 7, tl = idx & 127;
        float v = __ldg(x + ((size_t)b * CC + c) * TT + t0 + tl);
        *reinterpret_cast<__half*>(smem + K1_XS + tl * 132 + c * 2) = __float2half(v);
    }
    #pragma unroll
    for (int i = 0; i < 4; i++) {
        int g = i * 256 + tid;
        *reinterpret_cast<float*>(smem + K1_BS + g * 4) = g_b1[g];
    }
    __syncthreads();

    const int w = tid >> 5, lane = tid & 31;
    const int qr = lane >> 2, q4 = lane & 3;
    const int m0 = w * 16;

    uint32_t afr[4][4];
    {
        const char* xb = smem + K1_XS;
        #pragma unroll
        for (int kt = 0; kt < 4; kt++) {
            int kb = q4 * 2 + kt * 16;
            afr[kt][0] = *reinterpret_cast<const uint32_t*>(xb + (m0 + qr) * 132 + kb * 2);
            afr[kt][1] = *reinterpret_cast<const uint32_t*>(xb + (m0 + qr + 8) * 132 + kb * 2);
            afr[kt][2] = *reinterpret_cast<const uint32_t*>(xb + (m0 + qr) * 132 + (kb + 8) * 2);
            afr[kt][3] = *reinterpret_cast<const uint32_t*>(xb + (m0 + qr + 8) * 132 + (kb + 8) * 2);
        }
    }

    const char* wsb = smem + K1_WS;
    const int t_ = t0 + m0 + qr;
    const int bg = b >> 3, bi = b & 7;
    #pragma unroll 4
    for (int j = 0; j < 128; j++) {
        float acc[4] = {0.f, 0.f, 0.f, 0.f};
        int nr = j * 8 + qr;
        #pragma unroll
        for (int kt = 0; kt < 4; kt++) {
            int kb = q4 * 2 + kt * 16;
            uint32_t b0 = *reinterpret_cast<const uint32_t*>(wsb + nr * 144 + kb * 2);
            uint32_t b1 = *reinterpret_cast<const uint32_t*>(wsb + nr * 144 + (kb + 8) * 2);
            mma16816(acc, afr[kt], b0, b1, acc);
        }
        int gcol = j * 8 + q4 * 2;
        float2 bs = *reinterpret_cast<const float2*>(smem + K1_BS + gcol * 4);
        int dir = gcol >> 9, g = gcol & 511;
        g_z2[dir][bg][t_][g][bi]         = __float2half(acc[0] + bs.x);
        g_z2[dir][bg][t_][g + 1][bi]     = __float2half(acc[1] + bs.y);
        g_z2[dir][bg][t_ + 8][g][bi]     = __float2half(acc[2] + bs.x);
        g_z2[dir][bg][t_ + 8][g + 1][bi] = __float2half(acc[3] + bs.y);
    }
}

// ---------------- K2: recurrence — 8 chains/CTA, f16-acc mma, 4-deep chains -------
// 256 thr, 8 warps. Warp w owns gate rows q*128 + w*16 .. +15 for all 4 gates.
// B = h of 8 chains in smem. A = Whh fragments in regs (128). z = mma C operand
// (already f16, already in D layout). 8 accumulator sets (4 gates x 2 K-halves)
// -> dependent-mma chains of 4. Acts f16x2 MUFU; c state f32. One barrier/step.
__global__ void __launch_bounds__(256, 1) k2_hmma(
    const float* __restrict__ Whh_f, const float* __restrict__ Whh_b)
{
    const int bg = blockIdx.x, dir = blockIdx.y, tid = threadIdx.x;
    const float* Whh = dir ? Whh_b : Whh_f;
    const int w = tid >> 5, l = tid & 31;
    const int mrow = l >> 2;              // 0..7 (A/D row)
    const int kq   = (l & 3) * 2;         // frag k base / D col base (chain n0)
    const int ebase = w * 16;

    __shared__ __align__(16) __half hbuf[2][8][136];   // [buf][chain][k], 272B stride

    // A fragments: a[q][kt][4] — Whh rows q*128+ebase+mrow(+8), fp16
    uint32_t a[4][8][4];
    #pragma unroll
    for (int q = 0; q < 4; q++) {
        const float* W0 = Whh + (q * 128 + ebase + mrow) * HH;
        const float* W8 = W0 + 8 * HH;
        #pragma unroll
        for (int kt = 0; kt < 8; kt++) {
            int k0 = kt * 16 + kq;
            a[q][kt][0] = h2u(__floats2half2_rn(__ldg(W0 + k0),     __ldg(W0 + k0 + 1)));
            a[q][kt][1] = h2u(__floats2half2_rn(__ldg(W8 + k0),     __ldg(W8 + k0 + 1)));
            a[q][kt][2] = h2u(__floats2half2_rn(__ldg(W0 + k0 + 8), __ldg(W0 + k0 + 9)));
            a[q][kt][3] = h2u(__floats2half2_rn(__ldg(W8 + k0 + 8), __ldg(W8 + k0 + 9)));
        }
    }
    // zero h buffers
    for (int i = tid; i < 2 * 8 * 136; i += 256)
        reinterpret_cast<__half*>(hbuf)[i] = __float2half(0.f);
    float c[4] = {0.f, 0.f, 0.f, 0.f};
    __syncthreads();

    const __half* zb2 = &g_z2[dir][bg][0][0][0];
    int tt = dir ? (TT - 1) : 0;
    const int tstep = dir ? -1 : 1;
    const int yo = dir * HH;

    // depth-2 z prefetch: 8 LDG.32/lane (4 gates x 2 rows), coalesced
    uint32_t zr[8], zn[8];
    #pragma unroll
    for (int q = 0; q < 4; q++) {
        size_t o = ((size_t)tt * GG + (q * 128 + ebase + mrow)) * 8 + kq;
        zr[2*q]   = __ldg(reinterpret_cast<const uint32_t*>(zb2 + o));
        zr[2*q+1] = __ldg(reinterpret_cast<const uint32_t*>(zb2 + o + 64));
        size_t o2 = ((size_t)(tt + tstep) * GG + (q * 128 + ebase + mrow)) * 8 + kq;
        zn[2*q]   = __ldg(reinterpret_cast<const uint32_t*>(zb2 + o2));
        zn[2*q+1] = __ldg(reinterpret_cast<const uint32_t*>(zb2 + o2 + 64));
    }

    const __half2 H05 = __float2half2_rn(0.5f);

    for (int s = 0; s < TT; s++) {
        // B fragments for this step: h of 8 chains
        uint32_t bf0[8], bf1[8];
        const __half* hb = &hbuf[s & 1][mrow][0];
        #pragma unroll
        for (int kt = 0; kt < 8; kt++) {
            bf0[kt] = *reinterpret_cast<const uint32_t*>(hb + kt * 16 + kq);
            bf1[kt] = *reinterpret_cast<const uint32_t*>(hb + kt * 16 + kq + 8);
        }

        // accumulators: dA (K 0..63) init = z; dB (K 64..127) init = 0
        uint32_t dA[4][2], dB[4][2];
        #pragma unroll
        for (int q = 0; q < 4; q++) {
            dA[q][0] = zr[2*q];  dA[q][1] = zr[2*q+1];
            dB[q][0] = 0u;       dB[q][1] = 0u;
        }
        // rotate z prefetch
        #pragma unroll
        for (int r = 0; r < 8; r++) zr[r] = zn[r];
        if (s + 2 < TT) {
            #pragma unroll
            for (int q = 0; q < 4; q++) {
                size_t o = ((size_t)(tt + 2 * tstep) * GG + (q * 128 + ebase + mrow)) * 8 + kq;
                zn[2*q]   = __ldg(reinterpret_cast<const uint32_t*>(zb2 + o));
                zn[2*q+1] = __ldg(reinterpret_cast<const uint32_t*>(zb2 + o + 64));
            }
        }

        // 32 mma, 8 independent 4-deep chains
        #pragma unroll
        for (int kt = 0; kt < 4; kt++) {
            #pragma unroll
            for (int q = 0; q < 4; q++)
                mma16816h(dA[q], a[q][kt], bf0[kt], bf1[kt]);
            #pragma unroll
            for (int q = 0; q < 4; q++)
                mma16816h(dB[q], a[q][kt + 4], bf0[kt + 4], bf1[kt + 4]);
        }

        // combine halves + activations + state update
        // reg r: r=0 -> row mrow, r=1 -> row mrow+8; halves = chains kq, kq+1
        const int nb = (s + 1) & 1;
        #pragma unroll
        for (int r = 0; r < 2; r++) {
            __half2 zi = __hadd2(u2h(dA[0][r]), u2h(dB[0][r]));
            __half2 zf = __hadd2(u2h(dA[1][r]), u2h(dB[1][r]));
            __half2 zg = __hadd2(u2h(dA[2][r]), u2h(dB[2][r]));
            __half2 zo = __hadd2(u2h(dA[3][r]), u2h(dB[3][r]));
            __half2 si = __hfma2(h2tanh_(__hmul2(zi, H05)), H05, H05);
            __half2 sf = __hfma2(h2tanh_(__hmul2(zf, H05)), H05, H05);
            __half2 tg = h2tanh_(zg);
            __half2 so = __hfma2(h2tanh_(__hmul2(zo, H05)), H05, H05);

            float c0 = __low2float(sf)  * c[r*2]   + __low2float(si)  * __low2float(tg);
            float c1 = __high2float(sf) * c[r*2+1] + __high2float(si) * __high2float(tg);
            c[r*2] = c0; c[r*2+1] = c1;
            float h0 = __low2float(so)  * ftanh(c0);
            float h1 = __high2float(so) * ftanh(c1);
            __half hh0 = __float2half(h0);
            __half hh1 = __float2half(h1);

            int e = ebase + mrow + r * 8;
            hbuf[nb][kq][e]     = hh0;
            hbuf[nb][kq + 1][e] = hh1;
            g_y[bg * 8 + kq][tt][yo + e]     = hh0;
            g_y[bg * 8 + kq + 1][tt][yo + e] = hh1;
        }
        __syncthreads();
        tt += tstep;
    }
}

// ---------------- K3: attention logits via mma.sync ----------------
#define K3_WA   0
#define K3_YS   135168
#define K3_BW   202752
#define K3_TOT  204800

__global__ void __launch_bounds__(256) k3_mma(
    const float* __restrict__ ba, const float* __restrict__ Wu)
{
    extern __shared__ __align__(16) char smem[];
    const int tid = threadIdx.x;
    const int t0 = blockIdx.x * 128;
    const int b  = blockIdx.y;

    {
        const uint4* src = reinterpret_cast<const uint4*>(g_Wa_h);
        #pragma unroll
        for (int i = 0; i < 32; i++) {
            int idx = i * 256 + tid;
            int r = idx >> 5, c = idx & 31;
            *reinterpret_cast<uint4*>(smem + K3_WA + r * 528 + c * 16) = __ldg(src + idx);
        }
    }
    {
        const uint4* src = reinterpret_cast<const uint4*>(&g_y[b][t0][0]);
        #pragma unroll
        for (int i = 0; i < 16; i++) {
            int idx = i * 256 + tid;
            int r = idx >> 5, c = idx & 31;
            *reinterpret_cast<uint4*>(smem + K3_YS + r * 528 + c * 16) = src[idx];
        }
    }
    *reinterpret_cast<float2*>(smem + K3_BW + tid * 8) =
        make_float2(__ldg(ba + tid), __ldg(Wu + tid));
    __syncthreads();

    const int w = tid >> 5, lane = tid & 31;
    const int qr = lane >> 2, q4 = lane & 3;
    const int m0 = w * 16;

    uint32_t afr[16][4];
    {
        const char* yb = smem + K3_YS;
        #pragma unroll
        for (int kt = 0; kt < 16; kt++) {
            int kb = q4 * 2 + kt * 16;
            afr[kt][0] = *reinterpret_cast<const uint32_t*>(yb + (m0 + qr) * 528 + kb * 2);
            afr[kt][1] = *reinterpret_cast<const uint32_t*>(yb + (m0 + qr + 8) * 528 + kb * 2);
            afr[kt][2] = *reinterpret_cast<const uint32_t*>(yb + (m0 + qr) * 528 + (kb + 8) * 2);
            afr[kt][3] = *reinterpret_cast<const uint32_t*>(yb + (m0 + qr + 8) * 528 + (kb + 8) * 2);
        }
    }

    const char* wab = smem + K3_WA;
    const float2* bw = reinterpret_cast<const float2*>(smem + K3_BW);
    float s0 = 0.f, s1 = 0.f;

    #pragma unroll 2
    for (int j = 0; j < 32; j++) {
        float acc[4] = {0.f, 0.f, 0.f, 0.f};
        int nr = j * 8 + qr;
        #pragma unroll
        for (int kt = 0; kt < 16; kt++) {
            int kb = q4 * 2 + kt * 16;
            uint32_t b0 = *reinterpret_cast<const uint32_t*>(wab + nr * 528 + kb * 2);
            uint32_t b1 = *reinterpret_cast<const uint32_t*>(wab + nr * 528 + (kb + 8) * 2);
            mma16816(acc, afr[kt], b0, b1, acc);
        }
        int n0 = j * 8 + q4 * 2;
        float2 pp0 = bw[n0], pp1 = bw[n0 + 1];
        s0 += ftanh(acc[0] + pp0.x) * pp0.y + ftanh(acc[1] + pp1.x) * pp1.y;
        s1 += ftanh(acc[2] + pp0.x) * pp0.y + ftanh(acc[3] + pp1.x) * pp1.y;
    }
    s0 += __shfl_xor_sync(0xffffffffu, s0, 1);
    s0 += __shfl_xor_sync(0xffffffffu, s0, 2);
    s1 += __shfl_xor_sync(0xffffffffu, s1, 1);
    s1 += __shfl_xor_sync(0xffffffffu, s1, 2);
    if (q4 == 0) {
        g_scores[b][t0 + m0 + qr]     = s0;
        g_scores[b][t0 + m0 + qr + 8] = s1;
    }
}

// ---------------- K4: softmax over T + weighted sum ----------------
__global__ void __launch_bounds__(256) k4_soft(float* __restrict__ out)
{
    __shared__ float wb[TT];
    __shared__ float red[256];
    const int b = blockIdx.x, tid = threadIdx.x;

    float m = -1e30f;
    #pragma unroll
    for (int r = 0; r < 8; r++) m = fmaxf(m, g_scores[b][r * 256 + tid]);
    red[tid] = m; __syncthreads();
    for (int off = 128; off > 0; off >>= 1) {
        if (tid < off) red[tid] = fmaxf(red[tid], red[tid + off]);
        __syncthreads();
    }
    const float mx = red[0];
    __syncthreads();

    float ls = 0.f;
    #pragma unroll
    for (int r = 0; r < 8; r++) {
        int t = r * 256 + tid;
        float e = fast_ex2((g_scores[b][t] - mx) * LOG2E);
        wb[t] = e; ls += e;
    }
    red[tid] = ls; __syncthreads();
    for (int off = 128; off > 0; off >>= 1) {
        if (tid < off) red[tid] += red[tid + off];
        __syncthreads();
    }
    const float rz = __frcp_rn(red[0]);

    float acc = 0.f;
    const __half* yp = &g_y[b][0][tid];
    for (int t = 0; t < TT; t += 8) {
        #pragma unroll
        for (int u = 0; u < 8; u++)
            acc += wb[t + u] * __half2float(__ldg(yp + (size_t)(t + u) * H2));
    }
    out[b * H2 + tid] = acc * rz;
}

// ---------------- launch ----------------
extern "C" void kernel_launch(void* const* d_in, const int* in_sizes, int n_in,
                              void* d_out, int out_size)
{
    const float* x     = (const float*)d_in[0];
    const float* Wih_f = (const float*)d_in[1];
    const float* Whh_f = (const float*)d_in[2];
    const float* bih_f = (const float*)d_in[3];
    const float* bhh_f = (const float*)d_in[4];
    const float* Wih_b = (const float*)d_in[5];
    const float* Whh_b = (const float*)d_in[6];
    const float* bih_b = (const float*)d_in[7];
    const float* bhh_b = (const float*)d_in[8];
    const float* Wa    = (const float*)d_in[9];
    const float* ba    = (const float*)d_in[10];
    const float* Wu    = (const float*)d_in[11];
    float* out = (float*)d_out;

    cudaFuncSetAttribute(k1_mma, cudaFuncAttributeMaxDynamicSharedMemorySize, K1_TOT);
    cudaFuncSetAttribute(k3_mma, cudaFuncAttributeMaxDynamicSharedMemorySize, K3_TOT);

    p_prep<<<256, 256>>>(Wa, Wih_f, Wih_b, bih_f, bhh_f, bih_b, bhh_b);
    k1_mma<<<dim3(TT / 128, BB), 256, K1_TOT>>>(x);
    k2_hmma<<<dim3(BB / 8, 2), 256>>>(Whh_f, Whh_b);   // 8 chains/CTA, f16-acc mma
    k3_mma<<<dim3(TT / 128, BB), 256, K3_TOT>>>(ba, Wu);
    k4_soft<<<BB, 256>>>(out);
}

// round 14
// speedup vs baseline: 1.4479x; 1.4479x over previous
#include <cuda_runtime.h>
#include <cuda_fp16.h>
#include <cstdint>

#define BB 64
#define CC 64
#define TT 2048
#define HH 128
#define GG 512   // 4H
#define H2 256   // 2H

// Scratch (device globals — no runtime allocation allowed)
__device__ __half g_zin[2][BB][TT][GG];     // 256 MiB input projections (bias folded)
__device__ __half g_y[BB][TT][H2];          // 64 MiB [h_fwd | h_bwd]
__device__ float  g_scr4[4][BB][TT];        // attention logit partials (gate quarters)
__device__ __align__(16) __half g_Wa_h[H2 * H2];    // Wa fp16, row-major [g][k]
__device__ __align__(16) __half g_W1h[1024 * CC];   // [Wih_f; Wih_b] fp16 row-major
__device__ float  g_b1[1024];               // bih+bhh per dir, concatenated

// ---------------- helpers ----------------
__device__ __forceinline__ float fast_ex2(float x) {
    float y; asm("ex2.approx.f32 %0, %1;" : "=f"(y) : "f"(x)); return y;
}
#define LOG2E 1.4426950408889634f
__device__ __forceinline__ float ftanh(float x) {     // MUFU.TANH f32
    float y; asm("tanh.approx.f32 %0, %1;" : "=f"(y) : "f"(x)); return y;
}
__device__ __forceinline__ float fsigm(float x) {     // sigma via MUFU.TANH
    return fmaf(ftanh(0.5f * x), 0.5f, 0.5f);
}
__device__ __forceinline__ float hsum4(__half2 a, __half2 b, __half2 c, __half2 d) {
    __half2 s = __hadd2(__hadd2(a, b), __hadd2(c, d));
    return __low2float(s) + __high2float(s);
}
__device__ __forceinline__ __half2 u2h(unsigned u) {
    return *reinterpret_cast<__half2*>(&u);
}
__device__ __forceinline__ uint32_t h2u(__half2 h) {
    return *reinterpret_cast<uint32_t*>(&h);
}

// m16n8k16 row.col f16 -> f32 (base-target PTX, lowers to HMMA on sm_103)
__device__ __forceinline__ void mma16816(float* d, const uint32_t* a,
                                         uint32_t b0, uint32_t b1, const float* c) {
    asm volatile(
        "mma.sync.aligned.m16n8k16.row.col.f32.f16.f16.f32 "
        "{%0,%1,%2,%3}, {%4,%5,%6,%7}, {%8,%9}, {%10,%11,%12,%13};"
        : "=f"(d[0]), "=f"(d[1]), "=f"(d[2]), "=f"(d[3])
        : "r"(a[0]), "r"(a[1]), "r"(a[2]), "r"(a[3]),
          "r"(b0), "r"(b1),
          "f"(c[0]), "f"(c[1]), "f"(c[2]), "f"(c[3]));
}

// ---------------- prep: Wa + W1 + biases in one kernel ----------------
__global__ void __launch_bounds__(256) p_prep(
    const float* __restrict__ Wa,
    const float* __restrict__ Wf, const float* __restrict__ Wb,
    const float* __restrict__ bif, const float* __restrict__ bhf,
    const float* __restrict__ bib, const float* __restrict__ bhb)
{
    int i = blockIdx.x * 256 + threadIdx.x;           // 0..65535
    g_Wa_h[i] = __float2half(__ldg(Wa + i));
    g_W1h[i]  = __float2half(i < 32768 ? __ldg(Wf + i) : __ldg(Wb + i - 32768));
    if (i < 512)       g_b1[i] = __ldg(bif + i) + __ldg(bhf + i);
    else if (i < 1024) g_b1[i] = __ldg(bib + i - 512) + __ldg(bhb + i - 512);
}

// ---------------- K1: z = x_tile @ W1^T + bias — gate-split x2 for 2 CTAs/SM ------
// grid (T/128, B, 2); CTA z owns gate rows z*512 .. z*512+511.
#define K1_WS   0                        // 512 rows x 72 halfs = 73728 B
#define K1_XS   73728                    // 128 rows x 66 halfs = 16896 B
#define K1_BS   90624                    // 512 floats          = 2048 B
#define K1_TOT  92672

__global__ void __launch_bounds__(256) k1_mma(const float* __restrict__ x)
{
    extern __shared__ __align__(16) char smem[];
    const int tid = threadIdx.x;
    const int t0 = blockIdx.x * 128;
    const int b  = blockIdx.y;
    const int zoff = blockIdx.z * 512;   // gate-row offset

    {
        const uint4* src = reinterpret_cast<const uint4*>(g_W1h) + zoff * 8;
        #pragma unroll
        for (int i = 0; i < 16; i++) {
            int idx = i * 256 + tid;     // 0..4095 uint4 (512 rows x 8)
            int r = idx >> 3, c = idx & 7;
            *reinterpret_cast<uint4*>(smem + K1_WS + r * 144 + c * 16) = __ldg(src + idx);
        }
    }
    #pragma unroll
    for (int i = 0; i < 32; i++) {
        int idx = i * 256 + tid;
        int c = idx >> 7, tl = idx & 127;
        float v = __ldg(x + ((size_t)b * CC + c) * TT + t0 + tl);
        *reinterpret_cast<__half*>(smem + K1_XS + tl * 132 + c * 2) = __float2half(v);
    }
    #pragma unroll
    for (int i = 0; i < 2; i++) {
        int g = i * 256 + tid;
        *reinterpret_cast<float*>(smem + K1_BS + g * 4) = g_b1[zoff + g];
    }
    __syncthreads();

    const int w = tid >> 5, lane = tid & 31;
    const int qr = lane >> 2, q4 = lane & 3;
    const int m0 = w * 16;

    uint32_t afr[4][4];
    {
        const char* xb = smem + K1_XS;
        #pragma unroll
        for (int kt = 0; kt < 4; kt++) {
            int kb = q4 * 2 + kt * 16;
            afr[kt][0] = *reinterpret_cast<const uint32_t*>(xb + (m0 + qr) * 132 + kb * 2);
            afr[kt][1] = *reinterpret_cast<const uint32_t*>(xb + (m0 + qr + 8) * 132 + kb * 2);
            afr[kt][2] = *reinterpret_cast<const uint32_t*>(xb + (m0 + qr) * 132 + (kb + 8) * 2);
            afr[kt][3] = *reinterpret_cast<const uint32_t*>(xb + (m0 + qr + 8) * 132 + (kb + 8) * 2);
        }
    }

    const char* wsb = smem + K1_WS;
    const int t_ = t0 + m0 + qr;
    #pragma unroll 4
    for (int j = 0; j < 64; j++) {
        float acc[4] = {0.f, 0.f, 0.f, 0.f};
        int nr = j * 8 + qr;
        #pragma unroll
        for (int kt = 0; kt < 4; kt++) {
            int kb = q4 * 2 + kt * 16;
            uint32_t b0 = *reinterpret_cast<const uint32_t*>(wsb + nr * 144 + kb * 2);
            uint32_t b1 = *reinterpret_cast<const uint32_t*>(wsb + nr * 144 + (kb + 8) * 2);
            mma16816(acc, afr[kt], b0, b1, acc);
        }
        int gl = j * 8 + q4 * 2;                       // local gate col
        float2 bs = *reinterpret_cast<const float2*>(smem + K1_BS + gl * 4);
        int gcol = zoff + gl;
        int dir = gcol >> 9, g = gcol & 511;
        __half2 v01 = __floats2half2_rn(acc[0] + bs.x, acc[1] + bs.y);
        __half2 v23 = __floats2half2_rn(acc[2] + bs.x, acc[3] + bs.y);
        *reinterpret_cast<__half2*>(&g_zin[dir][b][t_][g]) = v01;
        *reinterpret_cast<__half2*>(&g_zin[dir][b][t_ + 8][g]) = v23;
    }
}

// ---------------- K2: recurrence — R10 best (HFMA2 + pipelined LDS + MUFU tail) ---
#define STEP4(v, k)                                              \
    p0 = __hfma2(w0[4*(k)+0], u2h((v).x), p0);                   \
    q0 = __hfma2(w1[4*(k)+0], u2h((v).x), q0);                   \
    p1 = __hfma2(w0[4*(k)+1], u2h((v).y), p1);                   \
    q1 = __hfma2(w1[4*(k)+1], u2h((v).y), q1);                   \
    p2 = __hfma2(w0[4*(k)+2], u2h((v).z), p2);                   \
    q2 = __hfma2(w1[4*(k)+2], u2h((v).z), q2);                   \
    p3 = __hfma2(w0[4*(k)+3], u2h((v).w), p3);                   \
    q3 = __hfma2(w1[4*(k)+3], u2h((v).w), q3);

__global__ void __launch_bounds__(256, 1) k2_lstm(
    const float* __restrict__ Whh_f, const float* __restrict__ Whh_b)
{
    const int b = blockIdx.x, dir = blockIdx.y, tid = threadIdx.x;
    const float* Whh = dir ? Whh_b : Whh_f;

    __shared__ __align__(16) __half hs[2][HH];

    const int w = tid >> 5, L = tid & 31;
    const int e  = w * 16 + (L & 15);
    const int hi = L >> 4;                 // 0: (i,f)+state  1: (g,o)
    const int row0 = e + hi * 256;         // i-row or g-row
    const int row1 = row0 + 128;           // f-row or o-row

    __half2 w0[64], w1[64];
    {
        const float4* P0 = reinterpret_cast<const float4*>(Whh + row0 * HH);
        const float4* P1 = reinterpret_cast<const float4*>(Whh + row1 * HH);
        #pragma unroll
        for (int k = 0; k < 32; k++) {
            float4 f = __ldg(P0 + k);
            w0[2*k]   = __floats2half2_rn(f.x, f.y);
            w0[2*k+1] = __floats2half2_rn(f.z, f.w);
            float4 g = __ldg(P1 + k);
            w1[2*k]   = __floats2half2_rn(g.x, g.y);
            w1[2*k+1] = __floats2half2_rn(g.z, g.w);
        }
    }
    if (tid < HH) {
        hs[0][tid] = __float2half(0.f);
        hs[1][tid] = __float2half(0.f);
    }
    float cst = 0.f;
    __syncthreads();

    const __half* zb = &g_zin[dir][b][0][0];
    int tt = dir ? (TT - 1) : 0;
    const int tstep = dir ? -1 : 1;
    __half* ydst = &g_y[b][0][dir * HH + e];

    float zc0 = __half2float(__ldg(zb + (size_t)tt * GG + row0));
    float zc1 = __half2float(__ldg(zb + (size_t)tt * GG + row1));
    float zn0 = __half2float(__ldg(zb + (size_t)(tt + tstep) * GG + row0));
    float zn1 = __half2float(__ldg(zb + (size_t)(tt + tstep) * GG + row1));

    for (int s = 0; s < TT; s++) {
        float a0 = zc0, a1 = zc1;
        zc0 = zn0; zc1 = zn1;
        if (s + 2 < TT) {
            const __half* zp = zb + (size_t)(tt + 2 * tstep) * GG;
            zn0 = __half2float(__ldg(zp + row0));
            zn1 = __half2float(__ldg(zp + row1));
        }

        const uint4* hr = reinterpret_cast<const uint4*>(&hs[s & 1][0]);
        const __half2 zz = __float2half2_rn(0.f);
        __half2 p0 = zz, p1 = zz, p2 = zz, p3 = zz;
        __half2 q0 = zz, q1 = zz, q2 = zz, q3 = zz;

        uint4 ha0 = hr[0],  ha1 = hr[1],  ha2 = hr[2],  ha3 = hr[3];
        uint4 hb0 = hr[4],  hb1 = hr[5],  hb2 = hr[6],  hb3 = hr[7];
        STEP4(ha0, 0)  STEP4(ha1, 1)  STEP4(ha2, 2)  STEP4(ha3, 3)
        ha0 = hr[8];  ha1 = hr[9];  ha2 = hr[10]; ha3 = hr[11];
        STEP4(hb0, 4)  STEP4(hb1, 5)  STEP4(hb2, 6)  STEP4(hb3, 7)
        hb0 = hr[12]; hb1 = hr[13]; hb2 = hr[14]; hb3 = hr[15];
        STEP4(ha0, 8)  STEP4(ha1, 9)  STEP4(ha2, 10) STEP4(ha3, 11)
        STEP4(hb0, 12) STEP4(hb1, 13) STEP4(hb2, 14) STEP4(hb3, 15)

        float s0 = a0 + hsum4(p0, p1, p2, p3);
        float s1 = a1 + hsum4(q0, q1, q2, q3);

        float n0 = hi ? ftanh(s0) : fsigm(s0);
        float n1 = fsigm(s1);
        uint32_t pk = h2u(__floats2half2_rn(n0, n1));
        uint32_t r  = __shfl_down_sync(0xffffffffu, pk, 16);

        if (hi == 0) {
            __half2 go = u2h(r);            // (tanh g, sigm o)
            float gv = __low2float(go), ov = __high2float(go);
            cst = n1 * cst + n0 * gv;
            float hv = ov * ftanh(cst);
            __half hh = __float2half(hv);
            hs[(s + 1) & 1][e] = hh;
            ydst[(size_t)tt * H2] = hh;
        }
        __syncthreads();
        tt += tstep;
    }
}

// ---------------- K3: attention logit partials — gate-split x4 for 2 CTAs/SM ------
// grid (T/128, B, 4); CTA q owns Wa rows q*64 .. q*64+63; partial -> g_scr4[q].
#define K3_WA   0                        // 64 rows x 264 halfs = 33792 B
#define K3_YS   33792                    // 128 rows x 264 halfs = 67584 B
#define K3_BW   101376                   // 64 float2            = 512 B
#define K3_TOT  101888

__global__ void __launch_bounds__(256) k3_mma(
    const float* __restrict__ ba, const float* __restrict__ Wu)
{
    extern __shared__ __align__(16) char smem[];
    const int tid = threadIdx.x;
    const int t0 = blockIdx.x * 128;
    const int b  = blockIdx.y;
    const int qid = blockIdx.z;          // gate quarter

    {
        const uint4* src = reinterpret_cast<const uint4*>(g_Wa_h) + qid * 64 * 32;
        #pragma unroll
        for (int i = 0; i < 8; i++) {
            int idx = i * 256 + tid;     // 0..2047 uint4 (64 rows x 32)
            int r = idx >> 5, c = idx & 31;
            *reinterpret_cast<uint4*>(smem + K3_WA + r * 528 + c * 16) = __ldg(src + idx);
        }
    }
    {
        const uint4* src = reinterpret_cast<const uint4*>(&g_y[b][t0][0]);
        #pragma unroll
        for (int i = 0; i < 16; i++) {
            int idx = i * 256 + tid;
            int r = idx >> 5, c = idx & 31;
            *reinterpret_cast<uint4*>(smem + K3_YS + r * 528 + c * 16) = src[idx];
        }
    }
    if (tid < 64)
        *reinterpret_cast<float2*>(smem + K3_BW + tid * 8) =
            make_float2(__ldg(ba + qid * 64 + tid), __ldg(Wu + qid * 64 + tid));
    __syncthreads();

    const int w = tid >> 5, lane = tid & 31;
    const int qr = lane >> 2, q4 = lane & 3;
    const int m0 = w * 16;

    uint32_t afr[16][4];
    {
        const char* yb = smem + K3_YS;
        #pragma unroll
        for (int kt = 0; kt < 16; kt++) {
            int kb = q4 * 2 + kt * 16;
            afr[kt][0] = *reinterpret_cast<const uint32_t*>(yb + (m0 + qr) * 528 + kb * 2);
            afr[kt][1] = *reinterpret_cast<const uint32_t*>(yb + (m0 + qr + 8) * 528 + kb * 2);
            afr[kt][2] = *reinterpret_cast<const uint32_t*>(yb + (m0 + qr) * 528 + (kb + 8) * 2);
            afr[kt][3] = *reinterpret_cast<const uint32_t*>(yb + (m0 + qr + 8) * 528 + (kb + 8) * 2);
        }
    }

    const char* wab = smem + K3_WA;
    const float2* bw = reinterpret_cast<const float2*>(smem + K3_BW);
    float s0 = 0.f, s1 = 0.f;

    #pragma unroll 2
    for (int j = 0; j < 8; j++) {        // 8 n-tiles = 64 gates (this quarter)
        float acc[4] = {0.f, 0.f, 0.f, 0.f};
        int nr = j * 8 + qr;
        #pragma unroll
        for (int kt = 0; kt < 16; kt++) {
            int kb = q4 * 2 + kt * 16;
            uint32_t b0 = *reinterpret_cast<const uint32_t*>(wab + nr * 528 + kb * 2);
            uint32_t b1 = *reinterpret_cast<const uint32_t*>(wab + nr * 528 + (kb + 8) * 2);
            mma16816(acc, afr[kt], b0, b1, acc);
        }
        int n0 = j * 8 + q4 * 2;
        float2 pp0 = bw[n0], pp1 = bw[n0 + 1];
        s0 += ftanh(acc[0] + pp0.x) * pp0.y + ftanh(acc[1] + pp1.x) * pp1.y;
        s1 += ftanh(acc[2] + pp0.x) * pp0.y + ftanh(acc[3] + pp1.x) * pp1.y;
    }
    s0 += __shfl_xor_sync(0xffffffffu, s0, 1);
    s0 += __shfl_xor_sync(0xffffffffu, s0, 2);
    s1 += __shfl_xor_sync(0xffffffffu, s1, 1);
    s1 += __shfl_xor_sync(0xffffffffu, s1, 2);
    if (q4 == 0) {
        g_scr4[qid][b][t0 + m0 + qr]     = s0;
        g_scr4[qid][b][t0 + m0 + qr + 8] = s1;
    }
}

// ---------------- K4: sum partials + softmax over T + weighted sum ----------------
__global__ void __launch_bounds__(256) k4_soft(float* __restrict__ out)
{
    __shared__ float wb[TT];
    __shared__ float red[256];
    const int b = blockIdx.x, tid = threadIdx.x;

    float m = -1e30f;
    #pragma unroll
    for (int r = 0; r < 8; r++) {
        int t = r * 256 + tid;
        float sc = g_scr4[0][b][t] + g_scr4[1][b][t] + g_scr4[2][b][t] + g_scr4[3][b][t];
        wb[t] = sc;
        m = fmaxf(m, sc);
    }
    red[tid] = m; __syncthreads();
    for (int off = 128; off > 0; off >>= 1) {
        if (tid < off) red[tid] = fmaxf(red[tid], red[tid + off]);
        __syncthreads();
    }
    const float mx = red[0];
    __syncthreads();

    float ls = 0.f;
    #pragma unroll
    for (int r = 0; r < 8; r++) {
        int t = r * 256 + tid;
        float e = fast_ex2((wb[t] - mx) * LOG2E);
        wb[t] = e; ls += e;
    }
    red[tid] = ls; __syncthreads();
    for (int off = 128; off > 0; off >>= 1) {
        if (tid < off) red[tid] += red[tid + off];
        __syncthreads();
    }
    const float rz = __frcp_rn(red[0]);
    __syncthreads();

    float acc = 0.f;
    const __half* yp = &g_y[b][0][tid];
    for (int t = 0; t < TT; t += 8) {
        #pragma unroll
        for (int u = 0; u < 8; u++)
            acc += wb[t + u] * __half2float(__ldg(yp + (size_t)(t + u) * H2));
    }
    out[b * H2 + tid] = acc * rz;
}

// ---------------- launch ----------------
extern "C" void kernel_launch(void* const* d_in, const int* in_sizes, int n_in,
                              void* d_out, int out_size)
{
    const float* x     = (const float*)d_in[0];
    const float* Wih_f = (const float*)d_in[1];
    const float* Whh_f = (const float*)d_in[2];
    const float* bih_f = (const float*)d_in[3];
    const float* bhh_f = (const float*)d_in[4];
    const float* Wih_b = (const float*)d_in[5];
    const float* Whh_b = (const float*)d_in[6];
    const float* bih_b = (const float*)d_in[7];
    const float* bhh_b = (const float*)d_in[8];
    const float* Wa    = (const float*)d_in[9];
    const float* ba    = (const float*)d_in[10];
    const float* Wu    = (const float*)d_in[11];
    float* out = (float*)d_out;

    cudaFuncSetAttribute(k1_mma, cudaFuncAttributeMaxDynamicSharedMemorySize, K1_TOT);
    cudaFuncSetAttribute(k3_mma, cudaFuncAttributeMaxDynamicSharedMemorySize, K3_TOT);

    p_prep<<<256, 256>>>(Wa, Wih_f, Wih_b, bih_f, bhh_f, bih_b, bhh_b);
    k1_mma<<<dim3(TT / 128, BB, 2), 256, K1_TOT>>>(x);
    k2_lstm<<<dim3(BB, 2), 256>>>(Whh_f, Whh_b);
    k3_mma<<<dim3(TT / 128, BB, 4), 256, K3_TOT>>>(ba, Wu);
    k4_soft<<<BB, 256>>>(out);
}

// round 15
// speedup vs baseline: 1.4886x; 1.0280x over previous
#include <cuda_runtime.h>
#include <cuda_fp16.h>
#include <cstdint>

#define BB 64
#define CC 64
#define TT 2048
#define HH 128
#define GG 512   // 4H
#define H2 256   // 2H

// Scratch (device globals — no runtime allocation allowed)
__device__ __half g_zin[2][BB][TT][GG];     // 256 MiB input projections (bias folded)
__device__ __half g_y[BB][TT][H2];          // 64 MiB [h_fwd | h_bwd]
__device__ float  g_scores[BB][TT];         // attention logits
__device__ __align__(16) __half g_Wa_h[H2 * H2];    // Wa fp16, row-major [g][k]
__device__ __align__(16) __half g_W1h[1024 * CC];   // [Wih_f; Wih_b] fp16 row-major
__device__ float  g_b1[1024];               // bih+bhh per dir, concatenated

// ---------------- helpers ----------------
__device__ __forceinline__ float fast_ex2(float x) {
    float y; asm("ex2.approx.f32 %0, %1;" : "=f"(y) : "f"(x)); return y;
}
#define LOG2E 1.4426950408889634f
__device__ __forceinline__ float ftanh(float x) {     // MUFU.TANH f32
    float y; asm("tanh.approx.f32 %0, %1;" : "=f"(y) : "f"(x)); return y;
}
__device__ __forceinline__ float fsigm(float x) {     // sigma via MUFU.TANH
    return fmaf(ftanh(0.5f * x), 0.5f, 0.5f);
}
__device__ __forceinline__ float hsum4(__half2 a, __half2 b, __half2 c, __half2 d) {
    __half2 s = __hadd2(__hadd2(a, b), __hadd2(c, d));
    return __low2float(s) + __high2float(s);
}
__device__ __forceinline__ __half2 u2h(unsigned u) {
    return *reinterpret_cast<__half2*>(&u);
}
__device__ __forceinline__ uint32_t h2u(__half2 h) {
    return *reinterpret_cast<uint32_t*>(&h);
}

// m16n8k16 row.col f16 -> f32 (base-target PTX, lowers to HMMA on sm_103)
__device__ __forceinline__ void mma16816(float* d, const uint32_t* a,
                                         uint32_t b0, uint32_t b1, const float* c) {
    asm volatile(
        "mma.sync.aligned.m16n8k16.row.col.f32.f16.f16.f32 "
        "{%0,%1,%2,%3}, {%4,%5,%6,%7}, {%8,%9}, {%10,%11,%12,%13};"
        : "=f"(d[0]), "=f"(d[1]), "=f"(d[2]), "=f"(d[3])
        : "r"(a[0]), "r"(a[1]), "r"(a[2]), "r"(a[3]),
          "r"(b0), "r"(b1),
          "f"(c[0]), "f"(c[1]), "f"(c[2]), "f"(c[3]));
}

// ---------------- prep: Wa + W1 + biases in one kernel ----------------
__global__ void __launch_bounds__(256) p_prep(
    const float* __restrict__ Wa,
    const float* __restrict__ Wf, const float* __restrict__ Wb,
    const float* __restrict__ bif, const float* __restrict__ bhf,
    const float* __restrict__ bib, const float* __restrict__ bhb)
{
    int i = blockIdx.x * 256 + threadIdx.x;           // 0..65535
    g_Wa_h[i] = __float2half(__ldg(Wa + i));
    g_W1h[i]  = __float2half(i < 32768 ? __ldg(Wf + i) : __ldg(Wb + i - 32768));
    if (i < 512)       g_b1[i] = __ldg(bif + i) + __ldg(bhf + i);
    else if (i < 1024) g_b1[i] = __ldg(bib + i - 512) + __ldg(bhb + i - 512);
}

// ---------------- K1: z = x_tile @ W1^T + bias, smem-staged coalesced stores ------
#define K1_WS   0                        // 1024 rows x 72 halfs = 147456 B
#define K1_XS   147456                   // 128 rows x 66 halfs  = 16896 B
#define K1_BS   164352                   // 1024 floats          = 4096 B
#define K1_ZS   168448                   // 128 rows x 136 halfs = 34816 B (z stage)
#define K1_TOT  203264

__global__ void __launch_bounds__(256) k1_mma(const float* __restrict__ x)
{
    extern __shared__ __align__(16) char smem[];
    const int tid = threadIdx.x;
    const int t0 = blockIdx.x * 128;
    const int b  = blockIdx.y;

    {
        const uint4* src = reinterpret_cast<const uint4*>(g_W1h);
        #pragma unroll
        for (int i = 0; i < 32; i++) {
            int idx = i * 256 + tid;
            int r = idx >> 3, c = idx & 7;
            *reinterpret_cast<uint4*>(smem + K1_WS + r * 144 + c * 16) = __ldg(src + idx);
        }
    }
    #pragma unroll
    for (int i = 0; i < 32; i++) {
        int idx = i * 256 + tid;
        int c = idx >> 7, tl = idx & 127;
        float v = __ldg(x + ((size_t)b * CC + c) * TT + t0 + tl);
        *reinterpret_cast<__half*>(smem + K1_XS + tl * 132 + c * 2) = __float2half(v);
    }
    #pragma unroll
    for (int i = 0; i < 4; i++) {
        int g = i * 256 + tid;
        *reinterpret_cast<float*>(smem + K1_BS + g * 4) = g_b1[g];
    }
    __syncthreads();

    const int w = tid >> 5, lane = tid & 31;
    const int qr = lane >> 2, q4 = lane & 3;
    const int m0 = w * 16;

    uint32_t afr[4][4];
    {
        const char* xb = smem + K1_XS;
        #pragma unroll
        for (int kt = 0; kt < 4; kt++) {
            int kb = q4 * 2 + kt * 16;
            afr[kt][0] = *reinterpret_cast<const uint32_t*>(xb + (m0 + qr) * 132 + kb * 2);
            afr[kt][1] = *reinterpret_cast<const uint32_t*>(xb + (m0 + qr + 8) * 132 + kb * 2);
            afr[kt][2] = *reinterpret_cast<const uint32_t*>(xb + (m0 + qr) * 132 + (kb + 8) * 2);
            afr[kt][3] = *reinterpret_cast<const uint32_t*>(xb + (m0 + qr + 8) * 132 + (kb + 8) * 2);
        }
    }

    const char* wsb = smem + K1_WS;
    char* zst = smem + K1_ZS;

    // 8 gate-chunks of 128; stage in smem, flush coalesced
    for (int jc = 0; jc < 8; jc++) {
        #pragma unroll 4
        for (int jj = 0; jj < 16; jj++) {
            int j = jc * 16 + jj;
            float acc[4] = {0.f, 0.f, 0.f, 0.f};
            int nr = j * 8 + qr;
            #pragma unroll
            for (int kt = 0; kt < 4; kt++) {
                int kb = q4 * 2 + kt * 16;
                uint32_t b0 = *reinterpret_cast<const uint32_t*>(wsb + nr * 144 + kb * 2);
                uint32_t b1 = *reinterpret_cast<const uint32_t*>(wsb + nr * 144 + (kb + 8) * 2);
                mma16816(acc, afr[kt], b0, b1, acc);
            }
            int gcol = j * 8 + q4 * 2;
            float2 bs = *reinterpret_cast<const float2*>(smem + K1_BS + gcol * 4);
            int gl = (j * 8 + q4 * 2) - jc * 128;       // 0..126 within chunk
            __half2 v01 = __floats2half2_rn(acc[0] + bs.x, acc[1] + bs.y);
            __half2 v23 = __floats2half2_rn(acc[2] + bs.x, acc[3] + bs.y);
            *reinterpret_cast<__half2*>(zst + (m0 + qr) * 272 + gl * 2) = v01;
            *reinterpret_cast<__half2*>(zst + (m0 + qr + 8) * 272 + gl * 2) = v23;
        }
        __syncthreads();
        // coalesced flush: 128 rows x 256B
        int dir = jc >> 2;
        int gbase = (jc & 3) * 128;
        #pragma unroll
        for (int i = 0; i < 8; i++) {
            int idx = i * 256 + tid;                    // 0..2047 uint4
            int r = idx >> 4, cc = idx & 15;
            uint4 v = *reinterpret_cast<const uint4*>(zst + r * 272 + cc * 16);
            *reinterpret_cast<uint4*>(&g_zin[dir][b][t0 + r][gbase + cc * 8]) = v;
        }
        __syncthreads();
    }
}

// ---------------- K2: recurrence — R10 best (HFMA2 + pipelined LDS + MUFU tail) ---
#define STEP4(v, k)                                              \
    p0 = __hfma2(w0[4*(k)+0], u2h((v).x), p0);                   \
    q0 = __hfma2(w1[4*(k)+0], u2h((v).x), q0);                   \
    p1 = __hfma2(w0[4*(k)+1], u2h((v).y), p1);                   \
    q1 = __hfma2(w1[4*(k)+1], u2h((v).y), q1);                   \
    p2 = __hfma2(w0[4*(k)+2], u2h((v).z), p2);                   \
    q2 = __hfma2(w1[4*(k)+2], u2h((v).z), q2);                   \
    p3 = __hfma2(w0[4*(k)+3], u2h((v).w), p3);                   \
    q3 = __hfma2(w1[4*(k)+3], u2h((v).w), q3);

__global__ void __launch_bounds__(256, 1) k2_lstm(
    const float* __restrict__ Whh_f, const float* __restrict__ Whh_b)
{
    const int b = blockIdx.x, dir = blockIdx.y, tid = threadIdx.x;
    const float* Whh = dir ? Whh_b : Whh_f;

    __shared__ __align__(16) __half hs[2][HH];

    const int w = tid >> 5, L = tid & 31;
    const int e  = w * 16 + (L & 15);
    const int hi = L >> 4;                 // 0: (i,f)+state  1: (g,o)
    const int row0 = e + hi * 256;         // i-row or g-row
    const int row1 = row0 + 128;           // f-row or o-row

    __half2 w0[64], w1[64];
    {
        const float4* P0 = reinterpret_cast<const float4*>(Whh + row0 * HH);
        const float4* P1 = reinterpret_cast<const float4*>(Whh + row1 * HH);
        #pragma unroll
        for (int k = 0; k < 32; k++) {
            float4 f = __ldg(P0 + k);
            w0[2*k]   = __floats2half2_rn(f.x, f.y);
            w0[2*k+1] = __floats2half2_rn(f.z, f.w);
            float4 g = __ldg(P1 + k);
            w1[2*k]   = __floats2half2_rn(g.x, g.y);
            w1[2*k+1] = __floats2half2_rn(g.z, g.w);
        }
    }
    if (tid < HH) {
        hs[0][tid] = __float2half(0.f);
        hs[1][tid] = __float2half(0.f);
    }
    float cst = 0.f;
    __syncthreads();

    const __half* zb = &g_zin[dir][b][0][0];
    int tt = dir ? (TT - 1) : 0;
    const int tstep = dir ? -1 : 1;
    __half* ydst = &g_y[b][0][dir * HH + e];

    float zc0 = __half2float(__ldg(zb + (size_t)tt * GG + row0));
    float zc1 = __half2float(__ldg(zb + (size_t)tt * GG + row1));
    float zn0 = __half2float(__ldg(zb + (size_t)(tt + tstep) * GG + row0));
    float zn1 = __half2float(__ldg(zb + (size_t)(tt + tstep) * GG + row1));

    for (int s = 0; s < TT; s++) {
        float a0 = zc0, a1 = zc1;
        zc0 = zn0; zc1 = zn1;
        if (s + 2 < TT) {
            const __half* zp = zb + (size_t)(tt + 2 * tstep) * GG;
            zn0 = __half2float(__ldg(zp + row0));
            zn1 = __half2float(__ldg(zp + row1));
        }

        const uint4* hr = reinterpret_cast<const uint4*>(&hs[s & 1][0]);
        const __half2 zz = __float2half2_rn(0.f);
        __half2 p0 = zz, p1 = zz, p2 = zz, p3 = zz;
        __half2 q0 = zz, q1 = zz, q2 = zz, q3 = zz;

        uint4 ha0 = hr[0],  ha1 = hr[1],  ha2 = hr[2],  ha3 = hr[3];
        uint4 hb0 = hr[4],  hb1 = hr[5],  hb2 = hr[6],  hb3 = hr[7];
        STEP4(ha0, 0)  STEP4(ha1, 1)  STEP4(ha2, 2)  STEP4(ha3, 3)
        ha0 = hr[8];  ha1 = hr[9];  ha2 = hr[10]; ha3 = hr[11];
        STEP4(hb0, 4)  STEP4(hb1, 5)  STEP4(hb2, 6)  STEP4(hb3, 7)
        hb0 = hr[12]; hb1 = hr[13]; hb2 = hr[14]; hb3 = hr[15];
        STEP4(ha0, 8)  STEP4(ha1, 9)  STEP4(ha2, 10) STEP4(ha3, 11)
        STEP4(hb0, 12) STEP4(hb1, 13) STEP4(hb2, 14) STEP4(hb3, 15)

        float s0 = a0 + hsum4(p0, p1, p2, p3);
        float s1 = a1 + hsum4(q0, q1, q2, q3);

        float n0 = hi ? ftanh(s0) : fsigm(s0);
        float n1 = fsigm(s1);
        uint32_t pk = h2u(__floats2half2_rn(n0, n1));
        uint32_t r  = __shfl_down_sync(0xffffffffu, pk, 16);

        if (hi == 0) {
            __half2 go = u2h(r);            // (tanh g, sigm o)
            float gv = __low2float(go), ov = __high2float(go);
            cst = n1 * cst + n0 * gv;
            float hv = ov * ftanh(cst);
            __half hh = __float2half(hv);
            hs[(s + 1) & 1][e] = hh;
            ydst[(size_t)tt * H2] = hh;
        }
        __syncthreads();
        tt += tstep;
    }
}

// ---------------- K3: attention logits via mma.sync (R10 unsplit) ----------------
#define K3_WA   0
#define K3_YS   135168
#define K3_BW   202752
#define K3_TOT  204800

__global__ void __launch_bounds__(256) k3_mma(
    const float* __restrict__ ba, const float* __restrict__ Wu)
{
    extern __shared__ __align__(16) char smem[];
    const int tid = threadIdx.x;
    const int t0 = blockIdx.x * 128;
    const int b  = blockIdx.y;

    {
        const uint4* src = reinterpret_cast<const uint4*>(g_Wa_h);
        #pragma unroll
        for (int i = 0; i < 32; i++) {
            int idx = i * 256 + tid;
            int r = idx >> 5, c = idx & 31;
            *reinterpret_cast<uint4*>(smem + K3_WA + r * 528 + c * 16) = __ldg(src + idx);
        }
    }
    {
        const uint4* src = reinterpret_cast<const uint4*>(&g_y[b][t0][0]);
        #pragma unroll
        for (int i = 0; i < 16; i++) {
            int idx = i * 256 + tid;
            int r = idx >> 5, c = idx & 31;
            *reinterpret_cast<uint4*>(smem + K3_YS + r * 528 + c * 16) = src[idx];
        }
    }
    *reinterpret_cast<float2*>(smem + K3_BW + tid * 8) =
        make_float2(__ldg(ba + tid), __ldg(Wu + tid));
    __syncthreads();

    const int w = tid >> 5, lane = tid & 31;
    const int qr = lane >> 2, q4 = lane & 3;
    const int m0 = w * 16;

    uint32_t afr[16][4];
    {
        const char* yb = smem + K3_YS;
        #pragma unroll
        for (int kt = 0; kt < 16; kt++) {
            int kb = q4 * 2 + kt * 16;
            afr[kt][0] = *reinterpret_cast<const uint32_t*>(yb + (m0 + qr) * 528 + kb * 2);
            afr[kt][1] = *reinterpret_cast<const uint32_t*>(yb + (m0 + qr + 8) * 528 + kb * 2);
            afr[kt][2] = *reinterpret_cast<const uint32_t*>(yb + (m0 + qr) * 528 + (kb + 8) * 2);
            afr[kt][3] = *reinterpret_cast<const uint32_t*>(yb + (m0 + qr + 8) * 528 + (kb + 8) * 2);
        }
    }

    const char* wab = smem + K3_WA;
    const float2* bw = reinterpret_cast<const float2*>(smem + K3_BW);
    float s0 = 0.f, s1 = 0.f;

    #pragma unroll 2
    for (int j = 0; j < 32; j++) {
        float acc[4] = {0.f, 0.f, 0.f, 0.f};
        int nr = j * 8 + qr;
        #pragma unroll
        for (int kt = 0; kt < 16; kt++) {
            int kb = q4 * 2 + kt * 16;
            uint32_t b0 = *reinterpret_cast<const uint32_t*>(wab + nr * 528 + kb * 2);
            uint32_t b1 = *reinterpret_cast<const uint32_t*>(wab + nr * 528 + (kb + 8) * 2);
            mma16816(acc, afr[kt], b0, b1, acc);
        }
        int n0 = j * 8 + q4 * 2;
        float2 pp0 = bw[n0], pp1 = bw[n0 + 1];
        s0 += ftanh(acc[0] + pp0.x) * pp0.y + ftanh(acc[1] + pp1.x) * pp1.y;
        s1 += ftanh(acc[2] + pp0.x) * pp0.y + ftanh(acc[3] + pp1.x) * pp1.y;
    }
    s0 += __shfl_xor_sync(0xffffffffu, s0, 1);
    s0 += __shfl_xor_sync(0xffffffffu, s0, 2);
    s1 += __shfl_xor_sync(0xffffffffu, s1, 1);
    s1 += __shfl_xor_sync(0xffffffffu, s1, 2);
    if (q4 == 0) {
        g_scores[b][t0 + m0 + qr]     = s0;
        g_scores[b][t0 + m0 + qr + 8] = s1;
    }
}

// ---------------- K4: softmax + weighted sum, channel/T split (grid B x 2) --------
__global__ void __launch_bounds__(256) k4_soft(float* __restrict__ out)
{
    __shared__ float wb[TT];
    __shared__ float red[256];
    const int b = blockIdx.x, half_ = blockIdx.y, tid = threadIdx.x;

    float m = -1e30f;
    #pragma unroll
    for (int r = 0; r < 8; r++) m = fmaxf(m, g_scores[b][r * 256 + tid]);
    red[tid] = m; __syncthreads();
    for (int off = 128; off > 0; off >>= 1) {
        if (tid < off) red[tid] = fmaxf(red[tid], red[tid + off]);
        __syncthreads();
    }
    const float mx = red[0];
    __syncthreads();

    float ls = 0.f;
    #pragma unroll
    for (int r = 0; r < 8; r++) {
        int t = r * 256 + tid;
        float e = fast_ex2((g_scores[b][t] - mx) * LOG2E);
        wb[t] = e; ls += e;
    }
    red[tid] = ls; __syncthreads();
    for (int off = 128; off > 0; off >>= 1) {
        if (tid < off) red[tid] += red[tid + off];
        __syncthreads();
    }
    const float rz = __frcp_rn(red[0]);
    __syncthreads();

    // channel ch over T-half th
    const int ch = half_ * 128 + (tid & 127);
    const int th = tid >> 7;
    const int tbase = th * 1024;
    float acc = 0.f;
    const __half* yp = &g_y[b][tbase][ch];
    for (int t = 0; t < 1024; t += 8) {
        #pragma unroll
        for (int u = 0; u < 8; u++)
            acc += wb[tbase + t + u] * __half2float(__ldg(yp + (size_t)(t + u) * H2));
    }
    red[tid] = acc;
    __syncthreads();
    if (tid < 128)
        out[b * H2 + half_ * 128 + tid] = (red[tid] + red[tid + 128]) * rz;
}

// ---------------- launch ----------------
extern "C" void kernel_launch(void* const* d_in, const int* in_sizes, int n_in,
                              void* d_out, int out_size)
{
    const float* x     = (const float*)d_in[0];
    const float* Wih_f = (const float*)d_in[1];
    const float* Whh_f = (const float*)d_in[2];
    const float* bih_f = (const float*)d_in[3];
    const float* bhh_f = (const float*)d_in[4];
    const float* Wih_b = (const float*)d_in[5];
    const float* Whh_b = (const float*)d_in[6];
    const float* bih_b = (const float*)d_in[7];
    const float* bhh_b = (const float*)d_in[8];
    const float* Wa    = (const float*)d_in[9];
    const float* ba    = (const float*)d_in[10];
    const float* Wu    = (const float*)d_in[11];
    float* out = (float*)d_out;

    cudaFuncSetAttribute(k1_mma, cudaFuncAttributeMaxDynamicSharedMemorySize, K1_TOT);
    cudaFuncSetAttribute(k3_mma, cudaFuncAttributeMaxDynamicSharedMemorySize, K3_TOT);

    p_prep<<<256, 256>>>(Wa, Wih_f, Wih_b, bih_f, bhh_f, bih_b, bhh_b);
    k1_mma<<<dim3(TT / 128, BB), 256, K1_TOT>>>(x);
    k2_lstm<<<dim3(BB, 2), 256>>>(Whh_f, Whh_b);
    k3_mma<<<dim3(TT / 128, BB), 256, K3_TOT>>>(ba, Wu);
    k4_soft<<<dim3(BB, 2), 256>>>(out);
}

// round 16
// speedup vs baseline: 1.4994x; 1.0073x over previous
#include <cuda_runtime.h>
#include <cuda_fp16.h>
#include <cstdint>

#define BB 64
#define CC 64
#define TT 2048
#define HH 128
#define GG 512   // 4H
#define H2 256   // 2H

// Scratch (device globals — no runtime allocation allowed)
__device__ __half g_zin[2][BB][TT][GG];     // 256 MiB input projections (bias folded)
__device__ __half g_y[BB][TT][H2];          // 64 MiB [h_fwd | h_bwd]
__device__ float  g_scores[BB][TT];         // attention logits
__device__ __align__(16) __half g_Wa_h[H2 * H2];    // Wa fp16, row-major [g][k]
__device__ __align__(16) __half g_W1h[1024 * CC];   // [Wih_f; Wih_b] fp16 row-major
__device__ float  g_b1[1024];               // bih+bhh per dir, concatenated

// ---------------- helpers ----------------
__device__ __forceinline__ float fast_ex2(float x) {
    float y; asm("ex2.approx.f32 %0, %1;" : "=f"(y) : "f"(x)); return y;
}
#define LOG2E 1.4426950408889634f
__device__ __forceinline__ float ftanh(float x) {     // MUFU.TANH f32
    float y; asm("tanh.approx.f32 %0, %1;" : "=f"(y) : "f"(x)); return y;
}
__device__ __forceinline__ float fsigm(float x) {     // sigma via MUFU.TANH
    return fmaf(ftanh(0.5f * x), 0.5f, 0.5f);
}
__device__ __forceinline__ float hsum4(__half2 a, __half2 b, __half2 c, __half2 d) {
    __half2 s = __hadd2(__hadd2(a, b), __hadd2(c, d));
    return __low2float(s) + __high2float(s);
}
__device__ __forceinline__ __half2 u2h(unsigned u) {
    return *reinterpret_cast<__half2*>(&u);
}
__device__ __forceinline__ uint32_t h2u(__half2 h) {
    return *reinterpret_cast<uint32_t*>(&h);
}

// m16n8k16 row.col f16 -> f32 (base-target PTX, lowers to HMMA on sm_103)
__device__ __forceinline__ void mma16816(float* d, const uint32_t* a,
                                         uint32_t b0, uint32_t b1, const float* c) {
    asm volatile(
        "mma.sync.aligned.m16n8k16.row.col.f32.f16.f16.f32 "
        "{%0,%1,%2,%3}, {%4,%5,%6,%7}, {%8,%9}, {%10,%11,%12,%13};"
        : "=f"(d[0]), "=f"(d[1]), "=f"(d[2]), "=f"(d[3])
        : "r"(a[0]), "r"(a[1]), "r"(a[2]), "r"(a[3]),
          "r"(b0), "r"(b1),
          "f"(c[0]), "f"(c[1]), "f"(c[2]), "f"(c[3]));
}

// ---------------- prep: Wa + W1 + biases in one kernel ----------------
__global__ void __launch_bounds__(256) p_prep(
    const float* __restrict__ Wa,
    const float* __restrict__ Wf, const float* __restrict__ Wb,
    const float* __restrict__ bif, const float* __restrict__ bhf,
    const float* __restrict__ bib, const float* __restrict__ bhb)
{
    int i = blockIdx.x * 256 + threadIdx.x;           // 0..65535
    g_Wa_h[i] = __float2half(__ldg(Wa + i));
    g_W1h[i]  = __float2half(i < 32768 ? __ldg(Wf + i) : __ldg(Wb + i - 32768));
    if (i < 512)       g_b1[i] = __ldg(bif + i) + __ldg(bhf + i);
    else if (i < 1024) g_b1[i] = __ldg(bib + i - 512) + __ldg(bhb + i - 512);
}

// ---------------- K1: z = x_tile @ W1^T + bias — W1 chunk-streamed, 3 CTAs/SM -----
#define K1_XS   0                        // 128 rows x 66 halfs  = 16896 B
#define K1_BS   16896                    // 1024 floats          = 4096 B
#define K1_ZS   20992                    // 128 rows x 136 halfs = 34816 B (z stage)
#define K1_WC   55808                    // 128 rows x 72 halfs  = 18432 B (W1 chunk)
#define K1_TOT  74240

__global__ void __launch_bounds__(256) k1_mma(const float* __restrict__ x)
{
    extern __shared__ __align__(16) char smem[];
    const int tid = threadIdx.x;
    const int t0 = blockIdx.x * 128;
    const int b  = blockIdx.y;

    // x tile: [c][t] fp32 -> smem [t][c] fp16
    #pragma unroll
    for (int i = 0; i < 32; i++) {
        int idx = i * 256 + tid;
        int c = idx >> 7, tl = idx & 127;
        float v = __ldg(x + ((size_t)b * CC + c) * TT + t0 + tl);
        *reinterpret_cast<__half*>(smem + K1_XS + tl * 132 + c * 2) = __float2half(v);
    }
    #pragma unroll
    for (int i = 0; i < 4; i++) {
        int g = i * 256 + tid;
        *reinterpret_cast<float*>(smem + K1_BS + g * 4) = g_b1[g];
    }
    __syncthreads();

    const int w = tid >> 5, lane = tid & 31;
    const int qr = lane >> 2, q4 = lane & 3;
    const int m0 = w * 16;

    uint32_t afr[4][4];
    {
        const char* xb = smem + K1_XS;
        #pragma unroll
        for (int kt = 0; kt < 4; kt++) {
            int kb = q4 * 2 + kt * 16;
            afr[kt][0] = *reinterpret_cast<const uint32_t*>(xb + (m0 + qr) * 132 + kb * 2);
            afr[kt][1] = *reinterpret_cast<const uint32_t*>(xb + (m0 + qr + 8) * 132 + kb * 2);
            afr[kt][2] = *reinterpret_cast<const uint32_t*>(xb + (m0 + qr) * 132 + (kb + 8) * 2);
            afr[kt][3] = *reinterpret_cast<const uint32_t*>(xb + (m0 + qr + 8) * 132 + (kb + 8) * 2);
        }
    }

    const char* wcb = smem + K1_WC;
    char* zst = smem + K1_ZS;

    // 8 gate-chunks of 128 rows: stream W1 chunk, mma, stage, flush coalesced
    for (int jc = 0; jc < 8; jc++) {
        // load W1 chunk: 128 rows x 8 uint4
        {
            const uint4* src = reinterpret_cast<const uint4*>(g_W1h) + jc * 1024;
            #pragma unroll
            for (int i = 0; i < 4; i++) {
                int idx = i * 256 + tid;
                int r = idx >> 3, c = idx & 7;
                *reinterpret_cast<uint4*>(smem + K1_WC + r * 144 + c * 16) = __ldg(src + idx);
            }
        }
        __syncthreads();

        #pragma unroll 4
        for (int j = 0; j < 16; j++) {
            float acc[4] = {0.f, 0.f, 0.f, 0.f};
            int nr = j * 8 + qr;
            #pragma unroll
            for (int kt = 0; kt < 4; kt++) {
                int kb = q4 * 2 + kt * 16;
                uint32_t b0 = *reinterpret_cast<const uint32_t*>(wcb + nr * 144 + kb * 2);
                uint32_t b1 = *reinterpret_cast<const uint32_t*>(wcb + nr * 144 + (kb + 8) * 2);
                mma16816(acc, afr[kt], b0, b1, acc);
            }
            int gl = j * 8 + q4 * 2;                        // 0..126 within chunk
            float2 bs = *reinterpret_cast<const float2*>(smem + K1_BS + (jc * 128 + gl) * 4);
            __half2 v01 = __floats2half2_rn(acc[0] + bs.x, acc[1] + bs.y);
            __half2 v23 = __floats2half2_rn(acc[2] + bs.x, acc[3] + bs.y);
            *reinterpret_cast<__half2*>(zst + (m0 + qr) * 272 + gl * 2) = v01;
            *reinterpret_cast<__half2*>(zst + (m0 + qr + 8) * 272 + gl * 2) = v23;
        }
        __syncthreads();
        // coalesced flush: 128 rows x 256B
        int dir = jc >> 2;
        int gbase = (jc & 3) * 128;
        #pragma unroll
        for (int i = 0; i < 8; i++) {
            int idx = i * 256 + tid;                        // 0..2047 uint4
            int r = idx >> 4, cc = idx & 15;
            uint4 v = *reinterpret_cast<const uint4*>(zst + r * 272 + cc * 16);
            *reinterpret_cast<uint4*>(&g_zin[dir][b][t0 + r][gbase + cc * 8]) = v;
        }
        __syncthreads();
    }
}

// ---------------- K2: recurrence — R10 best (HFMA2 + pipelined LDS + MUFU tail) ---
#define STEP4(v, k)                                              \
    p0 = __hfma2(w0[4*(k)+0], u2h((v).x), p0);                   \
    q0 = __hfma2(w1[4*(k)+0], u2h((v).x), q0);                   \
    p1 = __hfma2(w0[4*(k)+1], u2h((v).y), p1);                   \
    q1 = __hfma2(w1[4*(k)+1], u2h((v).y), q1);                   \
    p2 = __hfma2(w0[4*(k)+2], u2h((v).z), p2);                   \
    q2 = __hfma2(w1[4*(k)+2], u2h((v).z), q2);                   \
    p3 = __hfma2(w0[4*(k)+3], u2h((v).w), p3);                   \
    q3 = __hfma2(w1[4*(k)+3], u2h((v).w), q3);

__global__ void __launch_bounds__(256, 1) k2_lstm(
    const float* __restrict__ Whh_f, const float* __restrict__ Whh_b)
{
    const int b = blockIdx.x, dir = blockIdx.y, tid = threadIdx.x;
    const float* Whh = dir ? Whh_b : Whh_f;

    __shared__ __align__(16) __half hs[2][HH];

    const int w = tid >> 5, L = tid & 31;
    const int e  = w * 16 + (L & 15);
    const int hi = L >> 4;                 // 0: (i,f)+state  1: (g,o)
    const int row0 = e + hi * 256;         // i-row or g-row
    const int row1 = row0 + 128;           // f-row or o-row

    __half2 w0[64], w1[64];
    {
        const float4* P0 = reinterpret_cast<const float4*>(Whh + row0 * HH);
        const float4* P1 = reinterpret_cast<const float4*>(Whh + row1 * HH);
        #pragma unroll
        for (int k = 0; k < 32; k++) {
            float4 f = __ldg(P0 + k);
            w0[2*k]   = __floats2half2_rn(f.x, f.y);
            w0[2*k+1] = __floats2half2_rn(f.z, f.w);
            float4 g = __ldg(P1 + k);
            w1[2*k]   = __floats2half2_rn(g.x, g.y);
            w1[2*k+1] = __floats2half2_rn(g.z, g.w);
        }
    }
    if (tid < HH) {
        hs[0][tid] = __float2half(0.f);
        hs[1][tid] = __float2half(0.f);
    }
    float cst = 0.f;
    __syncthreads();

    const __half* zb = &g_zin[dir][b][0][0];
    int tt = dir ? (TT - 1) : 0;
    const int tstep = dir ? -1 : 1;
    __half* ydst = &g_y[b][0][dir * HH + e];

    float zc0 = __half2float(__ldg(zb + (size_t)tt * GG + row0));
    float zc1 = __half2float(__ldg(zb + (size_t)tt * GG + row1));
    float zn0 = __half2float(__ldg(zb + (size_t)(tt + tstep) * GG + row0));
    float zn1 = __half2float(__ldg(zb + (size_t)(tt + tstep) * GG + row1));

    for (int s = 0; s < TT; s++) {
        float a0 = zc0, a1 = zc1;
        zc0 = zn0; zc1 = zn1;
        if (s + 2 < TT) {
            const __half* zp = zb + (size_t)(tt + 2 * tstep) * GG;
            zn0 = __half2float(__ldg(zp + row0));
            zn1 = __half2float(__ldg(zp + row1));
        }

        const uint4* hr = reinterpret_cast<const uint4*>(&hs[s & 1][0]);
        const __half2 zz = __float2half2_rn(0.f);
        __half2 p0 = zz, p1 = zz, p2 = zz, p3 = zz;
        __half2 q0 = zz, q1 = zz, q2 = zz, q3 = zz;

        uint4 ha0 = hr[0],  ha1 = hr[1],  ha2 = hr[2],  ha3 = hr[3];
        uint4 hb0 = hr[4],  hb1 = hr[5],  hb2 = hr[6],  hb3 = hr[7];
        STEP4(ha0, 0)  STEP4(ha1, 1)  STEP4(ha2, 2)  STEP4(ha3, 3)
        ha0 = hr[8];  ha1 = hr[9];  ha2 = hr[10]; ha3 = hr[11];
        STEP4(hb0, 4)  STEP4(hb1, 5)  STEP4(hb2, 6)  STEP4(hb3, 7)
        hb0 = hr[12]; hb1 = hr[13]; hb2 = hr[14]; hb3 = hr[15];
        STEP4(ha0, 8)  STEP4(ha1, 9)  STEP4(ha2, 10) STEP4(ha3, 11)
        STEP4(hb0, 12) STEP4(hb1, 13) STEP4(hb2, 14) STEP4(hb3, 15)

        float s0 = a0 + hsum4(p0, p1, p2, p3);
        float s1 = a1 + hsum4(q0, q1, q2, q3);

        float n0 = hi ? ftanh(s0) : fsigm(s0);
        float n1 = fsigm(s1);
        uint32_t pk = h2u(__floats2half2_rn(n0, n1));
        uint32_t r  = __shfl_down_sync(0xffffffffu, pk, 16);

        if (hi == 0) {
            __half2 go = u2h(r);            // (tanh g, sigm o)
            float gv = __low2float(go), ov = __high2float(go);
            cst = n1 * cst + n0 * gv;
            float hv = ov * ftanh(cst);
            __half hh = __float2half(hv);
            hs[(s + 1) & 1][e] = hh;
            ydst[(size_t)tt * H2] = hh;
        }
        __syncthreads();
        tt += tstep;
    }
}

// ---------------- K3: attention logits — Wa chunk-streamed, 2 CTAs/SM ------------
#define K3_YS   0                        // 128 rows x 264 halfs = 67584 B
#define K3_BW   67584                    // 256 float2           = 2048 B
#define K3_WC   69632                    // 64 rows x 264 halfs  = 33792 B (Wa chunk)
#define K3_TOT  103424

__global__ void __launch_bounds__(256) k3_mma(
    const float* __restrict__ ba, const float* __restrict__ Wu)
{
    extern __shared__ __align__(16) char smem[];
    const int tid = threadIdx.x;
    const int t0 = blockIdx.x * 128;
    const int b  = blockIdx.y;

    {
        const uint4* src = reinterpret_cast<const uint4*>(&g_y[b][t0][0]);
        #pragma unroll
        for (int i = 0; i < 16; i++) {
            int idx = i * 256 + tid;
            int r = idx >> 5, c = idx & 31;
            *reinterpret_cast<uint4*>(smem + K3_YS + r * 528 + c * 16) = src[idx];
        }
    }
    *reinterpret_cast<float2*>(smem + K3_BW + tid * 8) =
        make_float2(__ldg(ba + tid), __ldg(Wu + tid));
    __syncthreads();

    const int w = tid >> 5, lane = tid & 31;
    const int qr = lane >> 2, q4 = lane & 3;
    const int m0 = w * 16;

    uint32_t afr[16][4];
    {
        const char* yb = smem + K3_YS;
        #pragma unroll
        for (int kt = 0; kt < 16; kt++) {
            int kb = q4 * 2 + kt * 16;
            afr[kt][0] = *reinterpret_cast<const uint32_t*>(yb + (m0 + qr) * 528 + kb * 2);
            afr[kt][1] = *reinterpret_cast<const uint32_t*>(yb + (m0 + qr + 8) * 528 + kb * 2);
            afr[kt][2] = *reinterpret_cast<const uint32_t*>(yb + (m0 + qr) * 528 + (kb + 8) * 2);
            afr[kt][3] = *reinterpret_cast<const uint32_t*>(yb + (m0 + qr + 8) * 528 + (kb + 8) * 2);
        }
    }

    const char* wcb = smem + K3_WC;
    const float2* bw = reinterpret_cast<const float2*>(smem + K3_BW);
    float s0 = 0.f, s1 = 0.f;

    for (int ch = 0; ch < 4; ch++) {
        __syncthreads();
        // load Wa chunk: rows ch*64..+63, 64 x 32 uint4
        {
            const uint4* src = reinterpret_cast<const uint4*>(g_Wa_h) + ch * 2048;
            #pragma unroll
            for (int i = 0; i < 8; i++) {
                int idx = i * 256 + tid;
                int r = idx >> 5, c = idx & 31;
                *reinterpret_cast<uint4*>(smem + K3_WC + r * 528 + c * 16) = __ldg(src + idx);
            }
        }
        __syncthreads();

        #pragma unroll 2
        for (int j = 0; j < 8; j++) {
            float acc[4] = {0.f, 0.f, 0.f, 0.f};
            int nr = j * 8 + qr;
            #pragma unroll
            for (int kt = 0; kt < 16; kt++) {
                int kb = q4 * 2 + kt * 16;
                uint32_t b0 = *reinterpret_cast<const uint32_t*>(wcb + nr * 528 + kb * 2);
                uint32_t b1 = *reinterpret_cast<const uint32_t*>(wcb + nr * 528 + (kb + 8) * 2);
                mma16816(acc, afr[kt], b0, b1, acc);
            }
            int n0 = ch * 64 + j * 8 + q4 * 2;
            float2 pp0 = bw[n0], pp1 = bw[n0 + 1];
            s0 += ftanh(acc[0] + pp0.x) * pp0.y + ftanh(acc[1] + pp1.x) * pp1.y;
            s1 += ftanh(acc[2] + pp0.x) * pp0.y + ftanh(acc[3] + pp1.x) * pp1.y;
        }
    }
    s0 += __shfl_xor_sync(0xffffffffu, s0, 1);
    s0 += __shfl_xor_sync(0xffffffffu, s0, 2);
    s1 += __shfl_xor_sync(0xffffffffu, s1, 1);
    s1 += __shfl_xor_sync(0xffffffffu, s1, 2);
    if (q4 == 0) {
        g_scores[b][t0 + m0 + qr]     = s0;
        g_scores[b][t0 + m0 + qr + 8] = s1;
    }
}

// ---------------- K4: softmax + weighted sum, channel/T split (grid B x 2) --------
__global__ void __launch_bounds__(256) k4_soft(float* __restrict__ out)
{
    __shared__ float wb[TT];
    __shared__ float red[256];
    const int b = blockIdx.x, half_ = blockIdx.y, tid = threadIdx.x;

    float m = -1e30f;
    #pragma unroll
    for (int r = 0; r < 8; r++) m = fmaxf(m, g_scores[b][r * 256 + tid]);
    red[tid] = m; __syncthreads();
    for (int off = 128; off > 0; off >>= 1) {
        if (tid < off) red[tid] = fmaxf(red[tid], red[tid + off]);
        __syncthreads();
    }
    const float mx = red[0];
    __syncthreads();

    float ls = 0.f;
    #pragma unroll
    for (int r = 0; r < 8; r++) {
        int t = r * 256 + tid;
        float e = fast_ex2((g_scores[b][t] - mx) * LOG2E);
        wb[t] = e; ls += e;
    }
    red[tid] = ls; __syncthreads();
    for (int off = 128; off > 0; off >>= 1) {
        if (tid < off) red[tid] += red[tid + off];
        __syncthreads();
    }
    const float rz = __frcp_rn(red[0]);
    __syncthreads();

    const int ch = half_ * 128 + (tid & 127);
    const int th = tid >> 7;
    const int tbase = th * 1024;
    float acc = 0.f;
    const __half* yp = &g_y[b][tbase][ch];
    for (int t = 0; t < 1024; t += 8) {
        #pragma unroll
        for (int u = 0; u < 8; u++)
            acc += wb[tbase + t + u] * __half2float(__ldg(yp + (size_t)(t + u) * H2));
    }
    red[tid] = acc;
    __syncthreads();
    if (tid < 128)
        out[b * H2 + half_ * 128 + tid] = (red[tid] + red[tid + 128]) * rz;
}

// ---------------- launch ----------------
extern "C" void kernel_launch(void* const* d_in, const int* in_sizes, int n_in,
                              void* d_out, int out_size)
{
    const float* x     = (const float*)d_in[0];
    const float* Wih_f = (const float*)d_in[1];
    const float* Whh_f = (const float*)d_in[2];
    const float* bih_f = (const float*)d_in[3];
    const float* bhh_f = (const float*)d_in[4];
    const float* Wih_b = (const float*)d_in[5];
    const float* Whh_b = (const float*)d_in[6];
    const float* bih_b = (const float*)d_in[7];
    const float* bhh_b = (const float*)d_in[8];
    const float* Wa    = (const float*)d_in[9];
    const float* ba    = (const float*)d_in[10];
    const float* Wu    = (const float*)d_in[11];
    float* out = (float*)d_out;

    cudaFuncSetAttribute(k1_mma, cudaFuncAttributeMaxDynamicSharedMemorySize, K1_TOT);
    cudaFuncSetAttribute(k3_mma, cudaFuncAttributeMaxDynamicSharedMemorySize, K3_TOT);

    p_prep<<<256, 256>>>(Wa, Wih_f, Wih_b, bih_f, bhh_f, bih_b, bhh_b);
    k1_mma<<<dim3(TT / 128, BB), 256, K1_TOT>>>(x);
    k2_lstm<<<dim3(BB, 2), 256>>>(Whh_f, Whh_b);
    k3_mma<<<dim3(TT / 128, BB), 256, K3_TOT>>>(ba, Wu);
    k4_soft<<<dim3(BB, 2), 256>>>(out);
}

// round 17
// speedup vs baseline: 1.5580x; 1.0391x over previous
#include <cuda_runtime.h>
#include <cuda_fp16.h>
#include <cstdint>

#define BB 64
#define CC 64
#define TT 2048
#define HH 128
#define GG 512   // 4H
#define H2 256   // 2H

// Scratch (device globals — no runtime allocation allowed)
__device__ __half g_zin[2][BB][TT][GG];     // 256 MiB input projections (bias folded)
__device__ __half g_y[BB][TT][H2];          // 64 MiB [h_fwd | h_bwd]
__device__ float  g_scores[BB][TT];         // attention logits
__device__ __align__(16) __half g_Wa_h[H2 * H2];    // Wa fp16, row-major [g][k]
__device__ __align__(16) __half g_W1h[1024 * CC];   // [Wih_f; Wih_b] fp16 row-major
__device__ float  g_b1[1024];               // bih+bhh per dir, concatenated

// ---------------- helpers ----------------
__device__ __forceinline__ float fast_ex2(float x) {
    float y; asm("ex2.approx.f32 %0, %1;" : "=f"(y) : "f"(x)); return y;
}
#define LOG2E 1.4426950408889634f
__device__ __forceinline__ float ftanh(float x) {     // MUFU.TANH f32
    float y; asm("tanh.approx.f32 %0, %1;" : "=f"(y) : "f"(x)); return y;
}
__device__ __forceinline__ float fsigm(float x) {     // sigma via MUFU.TANH
    return fmaf(ftanh(0.5f * x), 0.5f, 0.5f);
}
__device__ __forceinline__ float hsum4(__half2 a, __half2 b, __half2 c, __half2 d) {
    __half2 s = __hadd2(__hadd2(a, b), __hadd2(c, d));
    return __low2float(s) + __high2float(s);
}
__device__ __forceinline__ __half2 u2h(unsigned u) {
    return *reinterpret_cast<__half2*>(&u);
}
__device__ __forceinline__ uint32_t h2u(__half2 h) {
    return *reinterpret_cast<uint32_t*>(&h);
}

// m16n8k16 row.col f16 -> f32 (base-target PTX, lowers to HMMA on sm_103)
__device__ __forceinline__ void mma16816(float* d, const uint32_t* a,
                                         uint32_t b0, uint32_t b1, const float* c) {
    asm volatile(
        "mma.sync.aligned.m16n8k16.row.col.f32.f16.f16.f32 "
        "{%0,%1,%2,%3}, {%4,%5,%6,%7}, {%8,%9}, {%10,%11,%12,%13};"
        : "=f"(d[0]), "=f"(d[1]), "=f"(d[2]), "=f"(d[3])
        : "r"(a[0]), "r"(a[1]), "r"(a[2]), "r"(a[3]),
          "r"(b0), "r"(b1),
          "f"(c[0]), "f"(c[1]), "f"(c[2]), "f"(c[3]));
}

// ---------------- prep: Wa + W1 + biases in one kernel ----------------
__global__ void __launch_bounds__(256) p_prep(
    const float* __restrict__ Wa,
    const float* __restrict__ Wf, const float* __restrict__ Wb,
    const float* __restrict__ bif, const float* __restrict__ bhf,
    const float* __restrict__ bib, const float* __restrict__ bhb)
{
    int i = blockIdx.x * 256 + threadIdx.x;           // 0..65535
    g_Wa_h[i] = __float2half(__ldg(Wa + i));
    g_W1h[i]  = __float2half(i < 32768 ? __ldg(Wf + i) : __ldg(Wb + i - 32768));
    if (i < 512)       g_b1[i] = __ldg(bif + i) + __ldg(bhf + i);
    else if (i < 1024) g_b1[i] = __ldg(bib + i - 512) + __ldg(bhb + i - 512);
}

// ---------------- K1: z = x_tile @ W1^T + bias — W1 reg-prefetched chunks --------
#define K1_XS   0                        // 128 rows x 66 halfs  = 16896 B
#define K1_BS   16896                    // 1024 floats          = 4096 B
#define K1_ZS   20992                    // 128 rows x 136 halfs = 34816 B (z stage)
#define K1_WC   55808                    // 128 rows x 72 halfs  = 18432 B (W1 chunk)
#define K1_TOT  74240

__global__ void __launch_bounds__(256) k1_mma(const float* __restrict__ x)
{
    extern __shared__ __align__(16) char smem[];
    const int tid = threadIdx.x;
    const int t0 = blockIdx.x * 128;
    const int b  = blockIdx.y;

    // x tile: [c][t] fp32 -> smem [t][c] fp16
    #pragma unroll
    for (int i = 0; i < 32; i++) {
        int idx = i * 256 + tid;
        int c = idx >> 7, tl = idx & 127;
        float v = __ldg(x + ((size_t)b * CC + c) * TT + t0 + tl);
        *reinterpret_cast<__half*>(smem + K1_XS + tl * 132 + c * 2) = __float2half(v);
    }
    #pragma unroll
    for (int i = 0; i < 4; i++) {
        int g = i * 256 + tid;
        *reinterpret_cast<float*>(smem + K1_BS + g * 4) = g_b1[g];
    }

    // preload W1 chunk 0 into registers
    uint4 wreg[4];
    {
        const uint4* src = reinterpret_cast<const uint4*>(g_W1h);
        #pragma unroll
        for (int i = 0; i < 4; i++) wreg[i] = __ldg(src + i * 256 + tid);
    }
    __syncthreads();

    const int w = tid >> 5, lane = tid & 31;
    const int qr = lane >> 2, q4 = lane & 3;
    const int m0 = w * 16;

    uint32_t afr[4][4];
    {
        const char* xb = smem + K1_XS;
        #pragma unroll
        for (int kt = 0; kt < 4; kt++) {
            int kb = q4 * 2 + kt * 16;
            afr[kt][0] = *reinterpret_cast<const uint32_t*>(xb + (m0 + qr) * 132 + kb * 2);
            afr[kt][1] = *reinterpret_cast<const uint32_t*>(xb + (m0 + qr + 8) * 132 + kb * 2);
            afr[kt][2] = *reinterpret_cast<const uint32_t*>(xb + (m0 + qr) * 132 + (kb + 8) * 2);
            afr[kt][3] = *reinterpret_cast<const uint32_t*>(xb + (m0 + qr + 8) * 132 + (kb + 8) * 2);
        }
    }

    const char* wcb = smem + K1_WC;
    char* zst = smem + K1_ZS;

    // 8 gate-chunks of 128 rows: STS prefetched chunk, prefetch next, mma, flush
    for (int jc = 0; jc < 8; jc++) {
        // store current chunk regs -> smem
        #pragma unroll
        for (int i = 0; i < 4; i++) {
            int idx = i * 256 + tid;
            int r = idx >> 3, c = idx & 7;
            *reinterpret_cast<uint4*>(smem + K1_WC + r * 144 + c * 16) = wreg[i];
        }
        __syncthreads();
        // issue next chunk's loads (land under compute)
        if (jc < 7) {
            const uint4* src = reinterpret_cast<const uint4*>(g_W1h) + (jc + 1) * 1024;
            #pragma unroll
            for (int i = 0; i < 4; i++) wreg[i] = __ldg(src + i * 256 + tid);
        }

        #pragma unroll 4
        for (int j = 0; j < 16; j++) {
            float acc[4] = {0.f, 0.f, 0.f, 0.f};
            int nr = j * 8 + qr;
            #pragma unroll
            for (int kt = 0; kt < 4; kt++) {
                int kb = q4 * 2 + kt * 16;
                uint32_t b0 = *reinterpret_cast<const uint32_t*>(wcb + nr * 144 + kb * 2);
                uint32_t b1 = *reinterpret_cast<const uint32_t*>(wcb + nr * 144 + (kb + 8) * 2);
                mma16816(acc, afr[kt], b0, b1, acc);
            }
            int gl = j * 8 + q4 * 2;                        // 0..126 within chunk
            float2 bs = *reinterpret_cast<const float2*>(smem + K1_BS + (jc * 128 + gl) * 4);
            __half2 v01 = __floats2half2_rn(acc[0] + bs.x, acc[1] + bs.y);
            __half2 v23 = __floats2half2_rn(acc[2] + bs.x, acc[3] + bs.y);
            *reinterpret_cast<__half2*>(zst + (m0 + qr) * 272 + gl * 2) = v01;
            *reinterpret_cast<__half2*>(zst + (m0 + qr + 8) * 272 + gl * 2) = v23;
        }
        __syncthreads();
        // coalesced flush: 128 rows x 256B
        int dir = jc >> 2;
        int gbase = (jc & 3) * 128;
        #pragma unroll
        for (int i = 0; i < 8; i++) {
            int idx = i * 256 + tid;                        // 0..2047 uint4
            int r = idx >> 4, cc = idx & 15;
            uint4 v = *reinterpret_cast<const uint4*>(zst + r * 272 + cc * 16);
            *reinterpret_cast<uint4*>(&g_zin[dir][b][t0 + r][gbase + cc * 8]) = v;
        }
        __syncthreads();
    }
}

// ---------------- K2: recurrence — R10 best + branchless z prefetch --------------
#define STEP4(v, k)                                              \
    p0 = __hfma2(w0[4*(k)+0], u2h((v).x), p0);                   \
    q0 = __hfma2(w1[4*(k)+0], u2h((v).x), q0);                   \
    p1 = __hfma2(w0[4*(k)+1], u2h((v).y), p1);                   \
    q1 = __hfma2(w1[4*(k)+1], u2h((v).y), q1);                   \
    p2 = __hfma2(w0[4*(k)+2], u2h((v).z), p2);                   \
    q2 = __hfma2(w1[4*(k)+2], u2h((v).z), q2);                   \
    p3 = __hfma2(w0[4*(k)+3], u2h((v).w), p3);                   \
    q3 = __hfma2(w1[4*(k)+3], u2h((v).w), q3);

__global__ void __launch_bounds__(256, 1) k2_lstm(
    const float* __restrict__ Whh_f, const float* __restrict__ Whh_b)
{
    const int b = blockIdx.x, dir = blockIdx.y, tid = threadIdx.x;
    const float* Whh = dir ? Whh_b : Whh_f;

    __shared__ __align__(16) __half hs[2][HH];

    const int w = tid >> 5, L = tid & 31;
    const int e  = w * 16 + (L & 15);
    const int hi = L >> 4;                 // 0: (i,f)+state  1: (g,o)
    const int row0 = e + hi * 256;         // i-row or g-row
    const int row1 = row0 + 128;           // f-row or o-row

    __half2 w0[64], w1[64];
    {
        const float4* P0 = reinterpret_cast<const float4*>(Whh + row0 * HH);
        const float4* P1 = reinterpret_cast<const float4*>(Whh + row1 * HH);
        #pragma unroll
        for (int k = 0; k < 32; k++) {
            float4 f = __ldg(P0 + k);
            w0[2*k]   = __floats2half2_rn(f.x, f.y);
            w0[2*k+1] = __floats2half2_rn(f.z, f.w);
            float4 g = __ldg(P1 + k);
            w1[2*k]   = __floats2half2_rn(g.x, g.y);
            w1[2*k+1] = __floats2half2_rn(g.z, g.w);
        }
    }
    if (tid < HH) {
        hs[0][tid] = __float2half(0.f);
        hs[1][tid] = __float2half(0.f);
    }
    float cst = 0.f;
    __syncthreads();

    const __half* zb = &g_zin[dir][b][0][0];
    int tt = dir ? (TT - 1) : 0;
    const int tstep = dir ? -1 : 1;
    __half* ydst = &g_y[b][0][dir * HH + e];

    float zc0 = __half2float(__ldg(zb + (size_t)tt * GG + row0));
    float zc1 = __half2float(__ldg(zb + (size_t)tt * GG + row1));
    float zn0 = __half2float(__ldg(zb + (size_t)(tt + tstep) * GG + row0));
    float zn1 = __half2float(__ldg(zb + (size_t)(tt + tstep) * GG + row1));

    for (int s = 0; s < TT; s++) {
        float a0 = zc0, a1 = zc1;
        zc0 = zn0; zc1 = zn1;
        {   // branchless depth-2 prefetch (clamped; tail garbage never consumed)
            int t2 = tt + 2 * tstep;
            t2 = min(max(t2, 0), TT - 1);
            const __half* zp = zb + (size_t)t2 * GG;
            zn0 = __half2float(__ldg(zp + row0));
            zn1 = __half2float(__ldg(zp + row1));
        }

        const uint4* hr = reinterpret_cast<const uint4*>(&hs[s & 1][0]);
        const __half2 zz = __float2half2_rn(0.f);
        __half2 p0 = zz, p1 = zz, p2 = zz, p3 = zz;
        __half2 q0 = zz, q1 = zz, q2 = zz, q3 = zz;

        uint4 ha0 = hr[0],  ha1 = hr[1],  ha2 = hr[2],  ha3 = hr[3];
        uint4 hb0 = hr[4],  hb1 = hr[5],  hb2 = hr[6],  hb3 = hr[7];
        STEP4(ha0, 0)  STEP4(ha1, 1)  STEP4(ha2, 2)  STEP4(ha3, 3)
        ha0 = hr[8];  ha1 = hr[9];  ha2 = hr[10]; ha3 = hr[11];
        STEP4(hb0, 4)  STEP4(hb1, 5)  STEP4(hb2, 6)  STEP4(hb3, 7)
        hb0 = hr[12]; hb1 = hr[13]; hb2 = hr[14]; hb3 = hr[15];
        STEP4(ha0, 8)  STEP4(ha1, 9)  STEP4(ha2, 10) STEP4(ha3, 11)
        STEP4(hb0, 12) STEP4(hb1, 13) STEP4(hb2, 14) STEP4(hb3, 15)

        float s0 = a0 + hsum4(p0, p1, p2, p3);
        float s1 = a1 + hsum4(q0, q1, q2, q3);

        float n0 = hi ? ftanh(s0) : fsigm(s0);
        float n1 = fsigm(s1);
        uint32_t pk = h2u(__floats2half2_rn(n0, n1));
        uint32_t r  = __shfl_down_sync(0xffffffffu, pk, 16);

        if (hi == 0) {
            __half2 go = u2h(r);            // (tanh g, sigm o)
            float gv = __low2float(go), ov = __high2float(go);
            cst = n1 * cst + n0 * gv;
            float hv = ov * ftanh(cst);
            __half hh = __float2half(hv);
            hs[(s + 1) & 1][e] = hh;
            ydst[(size_t)tt * H2] = hh;
        }
        __syncthreads();
        tt += tstep;
    }
}

// ---------------- K3: attention logits — Wa chunk-streamed, 2 CTAs/SM ------------
#define K3_YS   0                        // 128 rows x 264 halfs = 67584 B
#define K3_BW   67584                    // 256 float2           = 2048 B
#define K3_WC   69632                    // 64 rows x 264 halfs  = 33792 B (Wa chunk)
#define K3_TOT  103424

__global__ void __launch_bounds__(256) k3_mma(
    const float* __restrict__ ba, const float* __restrict__ Wu)
{
    extern __shared__ __align__(16) char smem[];
    const int tid = threadIdx.x;
    const int t0 = blockIdx.x * 128;
    const int b  = blockIdx.y;

    {
        const uint4* src = reinterpret_cast<const uint4*>(&g_y[b][t0][0]);
        #pragma unroll
        for (int i = 0; i < 16; i++) {
            int idx = i * 256 + tid;
            int r = idx >> 5, c = idx & 31;
            *reinterpret_cast<uint4*>(smem + K3_YS + r * 528 + c * 16) = src[idx];
        }
    }
    *reinterpret_cast<float2*>(smem + K3_BW + tid * 8) =
        make_float2(__ldg(ba + tid), __ldg(Wu + tid));
    __syncthreads();

    const int w = tid >> 5, lane = tid & 31;
    const int qr = lane >> 2, q4 = lane & 3;
    const int m0 = w * 16;

    uint32_t afr[16][4];
    {
        const char* yb = smem + K3_YS;
        #pragma unroll
        for (int kt = 0; kt < 16; kt++) {
            int kb = q4 * 2 + kt * 16;
            afr[kt][0] = *reinterpret_cast<const uint32_t*>(yb + (m0 + qr) * 528 + kb * 2);
            afr[kt][1] = *reinterpret_cast<const uint32_t*>(yb + (m0 + qr + 8) * 528 + kb * 2);
            afr[kt][2] = *reinterpret_cast<const uint32_t*>(yb + (m0 + qr) * 528 + (kb + 8) * 2);
            afr[kt][3] = *reinterpret_cast<const uint32_t*>(yb + (m0 + qr + 8) * 528 + (kb + 8) * 2);
        }
    }

    const char* wcb = smem + K3_WC;
    const float2* bw = reinterpret_cast<const float2*>(smem + K3_BW);
    float s0 = 0.f, s1 = 0.f;

    for (int ch = 0; ch < 4; ch++) {
        __syncthreads();
        // load Wa chunk: rows ch*64..+63, 64 x 32 uint4
        {
            const uint4* src = reinterpret_cast<const uint4*>(g_Wa_h) + ch * 2048;
            #pragma unroll
            for (int i = 0; i < 8; i++) {
                int idx = i * 256 + tid;
                int r = idx >> 5, c = idx & 31;
                *reinterpret_cast<uint4*>(smem + K3_WC + r * 528 + c * 16) = __ldg(src + idx);
            }
        }
        __syncthreads();

        #pragma unroll 2
        for (int j = 0; j < 8; j++) {
            float acc[4] = {0.f, 0.f, 0.f, 0.f};
            int nr = j * 8 + qr;
            #pragma unroll
            for (int kt = 0; kt < 16; kt++) {
                int kb = q4 * 2 + kt * 16;
                uint32_t b0 = *reinterpret_cast<const uint32_t*>(wcb + nr * 528 + kb * 2);
                uint32_t b1 = *reinterpret_cast<const uint32_t*>(wcb + nr * 528 + (kb + 8) * 2);
                mma16816(acc, afr[kt], b0, b1, acc);
            }
            int n0 = ch * 64 + j * 8 + q4 * 2;
            float2 pp0 = bw[n0], pp1 = bw[n0 + 1];
            s0 += ftanh(acc[0] + pp0.x) * pp0.y + ftanh(acc[1] + pp1.x) * pp1.y;
            s1 += ftanh(acc[2] + pp0.x) * pp0.y + ftanh(acc[3] + pp1.x) * pp1.y;
        }
    }
    s0 += __shfl_xor_sync(0xffffffffu, s0, 1);
    s0 += __shfl_xor_sync(0xffffffffu, s0, 2);
    s1 += __shfl_xor_sync(0xffffffffu, s1, 1);
    s1 += __shfl_xor_sync(0xffffffffu, s1, 2);
    if (q4 == 0) {
        g_scores[b][t0 + m0 + qr]     = s0;
        g_scores[b][t0 + m0 + qr + 8] = s1;
    }
}

// ---------------- K4: softmax + weighted sum, channel/T split (grid B x 2) --------
__global__ void __launch_bounds__(256) k4_soft(float* __restrict__ out)
{
    __shared__ float wb[TT];
    __shared__ float red[256];
    const int b = blockIdx.x, half_ = blockIdx.y, tid = threadIdx.x;

    float m = -1e30f;
    #pragma unroll
    for (int r = 0; r < 8; r++) m = fmaxf(m, g_scores[b][r * 256 + tid]);
    red[tid] = m; __syncthreads();
    for (int off = 128; off > 0; off >>= 1) {
        if (tid < off) red[tid] = fmaxf(red[tid], red[tid + off]);
        __syncthreads();
    }
    const float mx = red[0];
    __syncthreads();

    float ls = 0.f;
    #pragma unroll
    for (int r = 0; r < 8; r++) {
        int t = r * 256 + tid;
        float e = fast_ex2((g_scores[b][t] - mx) * LOG2E);
        wb[t] = e; ls += e;
    }
    red[tid] = ls; __syncthreads();
    for (int off = 128; off > 0; off >>= 1) {
        if (tid < off) red[tid] += red[tid + off];
        __syncthreads();
    }
    const float rz = __frcp_rn(red[0]);
    __syncthreads();

    const int ch = half_ * 128 + (tid & 127);
    const int th = tid >> 7;
    const int tbase = th * 1024;
    float acc = 0.f;
    const __half* yp = &g_y[b][tbase][ch];
    for (int t = 0; t < 1024; t += 8) {
        #pragma unroll
        for (int u = 0; u < 8; u++)
            acc += wb[tbase + t + u] * __half2float(__ldg(yp + (size_t)(t + u) * H2));
    }
    red[tid] = acc;
    __syncthreads();
    if (tid < 128)
        out[b * H2 + half_ * 128 + tid] = (red[tid] + red[tid + 128]) * rz;
}

// ---------------- launch ----------------
extern "C" void kernel_launch(void* const* d_in, const int* in_sizes, int n_in,
                              void* d_out, int out_size)
{
    const float* x     = (const float*)d_in[0];
    const float* Wih_f = (const float*)d_in[1];
    const float* Whh_f = (const float*)d_in[2];
    const float* bih_f = (const float*)d_in[3];
    const float* bhh_f = (const float*)d_in[4];
    const float* Wih_b = (const float*)d_in[5];
    const float* Whh_b = (const float*)d_in[6];
    const float* bih_b = (const float*)d_in[7];
    const float* bhh_b = (const float*)d_in[8];
    const float* Wa    = (const float*)d_in[9];
    const float* ba    = (const float*)d_in[10];
    const float* Wu    = (const float*)d_in[11];
    float* out = (float*)d_out;

    cudaFuncSetAttribute(k1_mma, cudaFuncAttributeMaxDynamicSharedMemorySize, K1_TOT);
    cudaFuncSetAttribute(k3_mma, cudaFuncAttributeMaxDynamicSharedMemorySize, K3_TOT);

    p_prep<<<256, 256>>>(Wa, Wih_f, Wih_b, bih_f, bhh_f, bih_b, bhh_b);
    k1_mma<<<dim3(TT / 128, BB), 256, K1_TOT>>>(x);
    k2_lstm<<<dim3(BB, 2), 256>>>(Whh_f, Whh_b);
    k3_mma<<<dim3(TT / 128, BB), 256, K3_TOT>>>(ba, Wu);
    k4_soft<<<dim3(BB, 2), 256>>>(out);
}